// round 6
// baseline (speedup 1.0000x reference)
#include <cuda_runtime.h>
#include <cuda_bf16.h>
#include <mma.h>
#include <math.h>

using namespace nvcuda;

#define BB 128
#define TT 256
#define LL 512
#define HH 512
#define CC 95
#define ML 26

// ---------------- device scratch (static: no runtime allocation) ----------------
__device__ __align__(16) __nv_bfloat16 g_x16[BB * TT * LL];     // 32 MB
__device__ __align__(16) __nv_bfloat16 g_xEmb16[BB * TT * HH];  // 32 MB
__device__ __align__(16) __nv_bfloat16 g_Wi16[LL * HH];
__device__ __align__(16) __nv_bfloat16 g_Ws16[HH * HH];
__device__ __align__(16) __nv_bfloat16 g_Wih16[1536 * 1024];
__device__ __align__(16) __nv_bfloat16 g_Whh16[1536 * 512];
__device__ __align__(16) __nv_bfloat16 g_embSeq[ML * BB * HH];
__device__ __align__(16) float g_giEmb[ML * BB * 1536];         // 20 MB
__device__ __align__(16) float g_WoutT[CC * HH];
__device__ __align__(16) float g_h[BB * HH];
__device__ __align__(16) __nv_bfloat16 g_h16[BB * HH];
__device__ __align__(16) __nv_bfloat16 g_ctx16[BB * HH];
__device__ __align__(16) float g_gates[BB * 3072];
__device__ unsigned g_barcnt;

// ---------------- fast math ------------------------------------------------------
__device__ __forceinline__ float tanh_mufu(float x) {
    float y;
    asm("tanh.approx.f32 %0, %1;" : "=f"(y) : "f"(x));
    return y;
}

__device__ __forceinline__ float fast_rcp_pos(float q) {
    float r = __uint_as_float(0x7EF127EAu - __float_as_uint(q));
    r = r * (2.0f - q * r);
    r = r * (2.0f - q * r);
    return r;
}

__device__ __forceinline__ float fast_tanh(float x) {  // accurate FMA-only (GRU n)
    float cx = fminf(fmaxf(x, -7.90531110763549805f), 7.90531110763549805f);
    float x2 = cx * cx;
    float p = fmaf(x2, -8.60467152213735e-11f, 5.12229709037114e-08f);
    p = fmaf(p, x2, 1.48572235717979e-05f);
    p = fmaf(p, x2, 6.37261928875436e-04f);
    p = fmaf(p, x2, 4.89352455891786e-03f);
    p = cx * p;
    float q = fmaf(x2, 1.19825839466702e-06f, 1.18534705686654e-04f);
    q = fmaf(q, x2, 2.26843463243900e-03f);
    q = fmaf(q, x2, 4.89352518554385e-03f);
    return p * fast_rcp_pos(q);
}

// ---------------- one-time helpers -----------------------------------------------
__global__ void init_kernel() {
    int i = blockIdx.x * 512 + threadIdx.x;
    g_h[i] = 0.f;
    g_h16[i] = __float2bfloat16(0.f);
    if (i == 0) g_barcnt = 0u;
}

__global__ void f2bf_kernel(const float* __restrict__ src,
                            __nv_bfloat16* __restrict__ dst) {
    int i = (blockIdx.x * 256 + threadIdx.x) * 4;
    float4 v = *(const float4*)(src + i);
    __nv_bfloat162* o = (__nv_bfloat162*)(dst + i);
    o[0] = __floats2bfloat162_rn(v.x, v.y);
    o[1] = __floats2bfloat162_rn(v.z, v.w);
}

__global__ void convert_x_kernel(const float* __restrict__ x) {
    int i = (blockIdx.x * 256 + threadIdx.x) * 4;
    float4 v = *(const float4*)(x + i);
    __nv_bfloat162* o = (__nv_bfloat162*)(g_x16 + i);
    o[0] = __floats2bfloat162_rn(v.x, v.y);
    o[1] = __floats2bfloat162_rn(v.z, v.w);
}

__global__ void transpose_wout_kernel(const float* __restrict__ Wout) {
    int c = blockIdx.x;
    int k = threadIdx.x;
    g_WoutT[c * HH + k] = Wout[k * CC + c];
}

__global__ void embseq_kernel(const float* __restrict__ emb,
                              const int* __restrict__ targets) {
    int m = blockIdx.x;  // 0..3327
    int step = m >> 7, b = m & 127;
    int y = (step == 0) ? CC : targets[b * ML + step - 1];
    int k = threadIdx.x * 4;
    float4 v = *(const float4*)(emb + y * HH + k);
    __nv_bfloat162* o = (__nv_bfloat162*)(g_embSeq + (size_t)m * HH + k);
    o[0] = __floats2bfloat162_rn(v.x, v.y);
    o[1] = __floats2bfloat162_rn(v.z, v.w);
}

// ---------------- one-time: xEmb = x @ Wi + bi (bf16 wmma, 128x128 tiles) --------
__global__ void xemb_wmma_kernel(const float* __restrict__ bias) {
    extern __shared__ char dyn[];
    __nv_bfloat16 (*As)[32] = (__nv_bfloat16(*)[32])dyn;
    __nv_bfloat16 (*Bs)[128] = (__nv_bfloat16(*)[128])(dyn + 8192);
    float (*Co)[128] = (float(*)[128])(dyn + 16384);
    const int tid = threadIdx.x;
    const int wid = tid >> 5;
    const int m0 = blockIdx.y * 128;
    const int n0 = blockIdx.x * 128;
    const int warpM = wid & 3;
    const int warpN = wid >> 2;

    wmma::fragment<wmma::accumulator, 16, 16, 16, float> c[2][4];
#pragma unroll
    for (int i = 0; i < 2; ++i)
#pragma unroll
        for (int j = 0; j < 4; ++j) wmma::fill_fragment(c[i][j], 0.f);

    for (int k0 = 0; k0 < 512; k0 += 32) {
#pragma unroll
        for (int i = 0; i < 2; ++i) {
            int idx = tid + i * 256;
            int m = idx >> 2, kq = idx & 3;
            *(uint4*)&As[m][kq * 8] =
                *(const uint4*)&g_x16[(size_t)(m0 + m) * 512 + k0 + kq * 8];
        }
#pragma unroll
        for (int i = 0; i < 2; ++i) {
            int idx = tid + i * 256;
            int k = idx >> 4, q = idx & 15;
            *(uint4*)&Bs[k][q * 8] =
                *(const uint4*)&g_Wi16[(size_t)(k0 + k) * 512 + n0 + q * 8];
        }
        __syncthreads();
#pragma unroll
        for (int kk = 0; kk < 32; kk += 16) {
            wmma::fragment<wmma::matrix_a, 16, 16, 16, __nv_bfloat16, wmma::row_major> a[2];
            wmma::fragment<wmma::matrix_b, 16, 16, 16, __nv_bfloat16, wmma::row_major> b[4];
#pragma unroll
            for (int i = 0; i < 2; ++i)
                wmma::load_matrix_sync(a[i], &As[warpM * 32 + i * 16][kk], 32);
#pragma unroll
            for (int j = 0; j < 4; ++j)
                wmma::load_matrix_sync(b[j], &Bs[kk][warpN * 64 + j * 16], 128);
#pragma unroll
            for (int i = 0; i < 2; ++i)
#pragma unroll
                for (int j = 0; j < 4; ++j)
                    wmma::mma_sync(c[i][j], a[i], b[j], c[i][j]);
        }
        __syncthreads();
    }
#pragma unroll
    for (int i = 0; i < 2; ++i)
#pragma unroll
        for (int j = 0; j < 4; ++j)
            wmma::store_matrix_sync(&Co[warpM * 32 + i * 16][warpN * 64 + j * 16],
                                    c[i][j], 128, wmma::mem_row_major);
    __syncthreads();
#pragma unroll
    for (int it = 0; it < 64; ++it) {
        int idx = it * 256 + tid;
        int m = idx >> 7, cc = idx & 127;
        g_xEmb16[(size_t)(m0 + m) * 512 + n0 + cc] =
            __float2bfloat16(Co[m][cc] + bias[n0 + cc]);
    }
}

// ------ one-time: giEmb = embSeq @ W_ih[:, :512]^T  [3328,1536] fp32 -------------
__global__ void giemb_wmma_kernel() {
    __shared__ __nv_bfloat16 As[128][32];
    __shared__ __nv_bfloat16 Bs[64][32];
    const int tid = threadIdx.x;
    const int wid = tid >> 5;
    const int m0 = blockIdx.y * 128;
    const int n0 = blockIdx.x * 64;

    wmma::fragment<wmma::accumulator, 16, 16, 16, float> c[4];
#pragma unroll
    for (int j = 0; j < 4; ++j) wmma::fill_fragment(c[j], 0.f);

    for (int k0 = 0; k0 < 512; k0 += 32) {
#pragma unroll
        for (int i = 0; i < 2; ++i) {
            int idx = tid + i * 256;
            int m = idx >> 2, kq = idx & 3;
            *(uint4*)&As[m][kq * 8] =
                *(const uint4*)&g_embSeq[(size_t)(m0 + m) * 512 + k0 + kq * 8];
        }
        {
            int j = tid >> 2, kq = tid & 3;
            *(uint4*)&Bs[j][kq * 8] =
                *(const uint4*)&g_Wih16[(size_t)(n0 + j) * 1024 + k0 + kq * 8];
        }
        __syncthreads();
#pragma unroll
        for (int kk = 0; kk < 32; kk += 16) {
            wmma::fragment<wmma::matrix_a, 16, 16, 16, __nv_bfloat16, wmma::row_major> a;
            wmma::load_matrix_sync(a, &As[wid * 16][kk], 32);
#pragma unroll
            for (int j = 0; j < 4; ++j) {
                wmma::fragment<wmma::matrix_b, 16, 16, 16, __nv_bfloat16, wmma::col_major> bf;
                wmma::load_matrix_sync(bf, &Bs[j * 16][kk], 32);
                wmma::mma_sync(c[j], a, bf, c[j]);
            }
        }
        __syncthreads();
    }
#pragma unroll
    for (int j = 0; j < 4; ++j)
        wmma::store_matrix_sync(&g_giEmb[(size_t)(m0 + wid * 16) * 1536 + n0 + j * 16],
                                c[j], 1536, wmma::mem_row_major);
}

// =================================================================================
//                          THE PERSISTENT DECODE KERNEL
// =================================================================================

__device__ __forceinline__ void grid_bar(unsigned& target) {
    __syncthreads();
    target += 128u;
    if (threadIdx.x == 0) {
        __threadfence();
        atomicAdd(&g_barcnt, 1u);
        volatile unsigned* p = (volatile unsigned*)&g_barcnt;
        while (*p < target) {}
        __threadfence();
    }
    __syncthreads();
}

// attention body: e-scores (MUFU tanh) + softmax + ctx -> g_ctx16[b]
__device__ __forceinline__ void attn_body(int b, int tid,
                                          const float* sE, const float* wos,
                                          float* ew, float* red, float* redv,
                                          float* sPart, const float* bo) {
    {
        const int t = tid >> 2, q = tid & 3;
        const __nv_bfloat16* row =
            g_xEmb16 + ((size_t)(b * 256 + t)) * 512 + q * 128;
        float acc = 0.f;
#pragma unroll
        for (int i = 0; i < 16; ++i) {
            union { uint4 u; __nv_bfloat162 h2[4]; } U;
            U.u = *(const uint4*)&row[i * 8];
            int base = q * 128 + i * 8;
#pragma unroll
            for (int j = 0; j < 4; ++j) {
                float2 v = __bfloat1622float2(U.h2[j]);
                int idx = base + 2 * j;
                acc = fmaf(wos[idx], tanh_mufu(v.x + sE[idx]), acc);
                acc = fmaf(wos[idx + 1], tanh_mufu(v.y + sE[idx + 1]), acc);
            }
        }
        acc += __shfl_xor_sync(0xffffffffu, acc, 1);
        acc += __shfl_xor_sync(0xffffffffu, acc, 2);
        if (q == 0) ew[t] = acc + bo[0];
    }
    __syncthreads();

    if (tid < 256) {
        float v = ew[tid];
        float m = v;
#pragma unroll
        for (int off = 16; off > 0; off >>= 1)
            m = fmaxf(m, __shfl_xor_sync(0xffffffffu, m, off));
        if ((tid & 31) == 0) red[tid >> 5] = m;
    }
    __syncthreads();
    if (tid == 0) {
        float m = red[0];
#pragma unroll
        for (int w = 1; w < 8; ++w) m = fmaxf(m, red[w]);
        redv[0] = m;
    }
    __syncthreads();
    if (tid < 256) {
        float p = __expf(ew[tid] - redv[0]);
        ew[tid] = p;
        float s = p;
#pragma unroll
        for (int off = 16; off > 0; off >>= 1)
            s += __shfl_xor_sync(0xffffffffu, s, off);
        if ((tid & 31) == 0) red[8 + (tid >> 5)] = s;
    }
    __syncthreads();
    if (tid == 0) {
        float s = 0.f;
#pragma unroll
        for (int w = 0; w < 8; ++w) s += red[8 + w];
        redv[1] = 1.0f / s;
    }
    __syncthreads();
    if (tid < 256) ew[tid] *= redv[1];
    __syncthreads();

    {
        const int d2 = tid & 255, tq = tid >> 8;
        const __nv_bfloat162* xb =
            (const __nv_bfloat162*)g_x16 + ((size_t)b * 256 + tq * 64) * 256 + d2;
        float ax = 0.f, ay = 0.f;
#pragma unroll 8
        for (int tt = 0; tt < 64; ++tt) {
            float a = ew[tq * 64 + tt];
            float2 v = __bfloat1622float2(xb[(size_t)tt * 256]);
            ax = fmaf(a, v.x, ax);
            ay = fmaf(a, v.y, ay);
        }
        sPart[tq * 512 + 2 * d2] = ax;
        sPart[tq * 512 + 2 * d2 + 1] = ay;
    }
    __syncthreads();
    if (tid < 512) {
        float c = sPart[tid] + sPart[512 + tid] + sPart[1024 + tid] + sPart[1536 + tid];
        g_ctx16[b * 512 + tid] = __float2bfloat16(c);
    }
}

// output (logits + log-softmax) for nrows batch rows starting at b0
__device__ __forceinline__ void out_rows(const float* __restrict__ bout,
                                         float* __restrict__ out, int step,
                                         int b0, int nrows, int tid,
                                         float* sbuf) {
    float* hbuf = sbuf;                    // nrows*512
    float* partb = sbuf + 2048;            // nrows*192
    float* lgb = sbuf + 2048 + 768;        // nrows*96
    for (int i = tid; i < nrows * 512; i += 1024)
        hbuf[i] = g_h[(size_t)(b0 + (i >> 9)) * 512 + (i & 511)];
    __syncthreads();
    if (tid < nrows * 190) {
        int r = tid / 190, j = tid % 190, c = j >> 1, ks = j & 1;
        const float4* wp = (const float4*)(g_WoutT + c * 512 + ks * 256);
        const float4* hp = (const float4*)(hbuf + r * 512 + ks * 256);
        float acc = 0.f;
#pragma unroll 8
        for (int k = 0; k < 64; ++k) {
            float4 h4 = hp[k], w4 = wp[k];
            acc = fmaf(h4.x, w4.x, acc);
            acc = fmaf(h4.y, w4.y, acc);
            acc = fmaf(h4.z, w4.z, acc);
            acc = fmaf(h4.w, w4.w, acc);
        }
        partb[r * 192 + j] = acc;
    }
    __syncthreads();
    if (tid < nrows * 95) {
        int r = tid / 95, c = tid % 95;
        lgb[r * 96 + c] = partb[r * 192 + 2 * c] + partb[r * 192 + 2 * c + 1] + bout[c];
    }
    __syncthreads();
    int warp = tid >> 5, lane = tid & 31;
    if (warp < nrows) {
        float v0 = (lane < 95) ? lgb[warp * 96 + lane] : -1e30f;
        float v1 = (lane + 32 < 95) ? lgb[warp * 96 + lane + 32] : -1e30f;
        float v2 = (lane + 64 < 95) ? lgb[warp * 96 + lane + 64] : -1e30f;
        float m = fmaxf(v0, fmaxf(v1, v2));
#pragma unroll
        for (int off = 16; off > 0; off >>= 1)
            m = fmaxf(m, __shfl_xor_sync(0xffffffffu, m, off));
        float s = ((lane < 95) ? __expf(v0 - m) : 0.f) +
                  ((lane + 32 < 95) ? __expf(v1 - m) : 0.f) +
                  ((lane + 64 < 95) ? __expf(v2 - m) : 0.f);
#pragma unroll
        for (int off = 16; off > 0; off >>= 1)
            s += __shfl_xor_sync(0xffffffffu, s, off);
        float lse = m + logf(s);
        float* o = out + (size_t)step * BB * CC + (size_t)(b0 + warp) * CC;
        if (lane < 95) o[lane] = v0 - lse;
        if (lane + 32 < 95) o[lane + 32] = v1 - lse;
        if (lane + 64 < 95) o[lane + 64] = v2 - lse;
    }
    __syncthreads();
}

__global__ __launch_bounds__(1024, 1)
void persistent_kernel(const float* __restrict__ b_ih,
                       const float* __restrict__ b_hh,
                       const float* __restrict__ bout,
                       const float* __restrict__ wo,
                       const float* __restrict__ bo,
                       const float* __restrict__ bs,
                       float* __restrict__ out) {
    const int bid = blockIdx.x;
    const int tid = threadIdx.x;
    __shared__ float sPart[8 * 512];              // 16 KB (sEmb / ctx / out scratch)
    __shared__ __nv_bfloat16 As[128][32];         // 8 KB (gates)
    __shared__ __nv_bfloat16 Bs[32][32];          // 2 KB (gates)
    __shared__ float hs[512], sE[512], wos[512], ew[256];
    __shared__ float red[16], redv[2];
    unsigned target = 0;

    if (tid < 512) {
        wos[tid] = wo[tid];
        hs[tid] = 0.f;
        sE[tid] = bs[tid];  // h=0 -> sEmb = bs
    }
    __syncthreads();

    // ---- attention for step 0 ----
    attn_body(bid, tid, sE, wos, ew, red, redv, sPart, bo);
    grid_bar(target);

    for (int step = 0; step < ML; ++step) {
        // ============ Phase G: gates tiles (blocks 0-95) | out(step-1) (96-127) ==
        if (bid < 96) {
            const bool hh = bid >= 48;
            const __nv_bfloat16* A = hh ? g_h16 : g_ctx16;
            const __nv_bfloat16* W = hh ? g_Whh16 : g_Wih16;
            const int ldw = hh ? 512 : 1024;
            const int koff = hh ? 0 : 512;
            const int n0 = (hh ? bid - 48 : bid) * 32;
            const int outc = (hh ? 1536 : 0) + n0;
            const int wid = tid >> 5;

            wmma::fragment<wmma::accumulator, 16, 16, 16, float> c[2];
            if (tid < 256) {
                if (hh) {
                    wmma::fill_fragment(c[0], 0.f);
                    wmma::fill_fragment(c[1], 0.f);
                } else {
                    const float* gi =
                        g_giEmb + ((size_t)step * 128 + wid * 16) * 1536 + n0;
                    wmma::load_matrix_sync(c[0], gi, 1536, wmma::mem_row_major);
                    wmma::load_matrix_sync(c[1], gi + 16, 1536, wmma::mem_row_major);
                }
            }
            for (int k0 = 0; k0 < 512; k0 += 32) {
                if (tid < 512) {
                    int m = tid >> 2, kq = tid & 3;
                    *(uint4*)&As[m][kq * 8] =
                        *(const uint4*)&A[(size_t)m * 512 + k0 + kq * 8];
                }
                if (tid < 128) {
                    int j = tid >> 2, kq = tid & 3;
                    *(uint4*)&Bs[j][kq * 8] =
                        *(const uint4*)&W[(size_t)(n0 + j) * ldw + koff + k0 + kq * 8];
                }
                __syncthreads();
                if (tid < 256) {
#pragma unroll
                    for (int kk = 0; kk < 32; kk += 16) {
                        wmma::fragment<wmma::matrix_a, 16, 16, 16, __nv_bfloat16,
                                       wmma::row_major> a;
                        wmma::load_matrix_sync(a, &As[wid * 16][kk], 32);
#pragma unroll
                        for (int j = 0; j < 2; ++j) {
                            wmma::fragment<wmma::matrix_b, 16, 16, 16, __nv_bfloat16,
                                           wmma::col_major> bf;
                            wmma::load_matrix_sync(bf, &Bs[j * 16][kk], 32);
                            wmma::mma_sync(c[j], a, bf, c[j]);
                        }
                    }
                }
                __syncthreads();
            }
            if (tid < 256) {
#pragma unroll
                for (int j = 0; j < 2; ++j)
                    wmma::store_matrix_sync(
                        &g_gates[(size_t)(wid * 16) * 3072 + outc + j * 16],
                        c[j], 3072, wmma::mem_row_major);
            }
        } else if (step > 0) {
            out_rows(bout, out, step - 1, (bid - 96) * 4, 4, tid, sPart);
        }
        grid_bar(target);

        // ============ Phase F: GRU pointwise + (sEmb + attention for next step) ==
        if (tid < 512) {
            const float* g = g_gates + bid * 3072;
            float gir = g[tid] + b_ih[tid];
            float giz = g[tid + 512] + b_ih[tid + 512];
            float gin = g[tid + 1024] + b_ih[tid + 1024];
            float ghr = g[tid + 1536] + b_hh[tid];
            float ghz = g[tid + 2048] + b_hh[tid + 512];
            float ghn = g[tid + 2560] + b_hh[tid + 1024];
            float r = 1.f / (1.f + __expf(-(gir + ghr)));
            float z = 1.f / (1.f + __expf(-(giz + ghz)));
            float n = fast_tanh(gin + r * ghn);
            float hv = (1.f - z) * n + z * hs[tid];
            g_h[bid * 512 + tid] = hv;
            g_h16[bid * 512 + tid] = __float2bfloat16(hv);
            hs[tid] = hv;
        }
        __syncthreads();

        if (step < ML - 1) {
            // sEmb = h @ Ws + bs (8-way k-split over 1024 threads)
            {
                const int ks = tid >> 7;          // 0..7
                const int n0 = (tid & 127) * 4;   // 0..508
                float acc0 = 0.f, acc1 = 0.f, acc2 = 0.f, acc3 = 0.f;
#pragma unroll 4
                for (int kk = 0; kk < 64; ++kk) {
                    int k = ks * 64 + kk;
                    float hk = hs[k];
                    union { uint2 u; __nv_bfloat162 h2[2]; } U;
                    U.u = *(const uint2*)&g_Ws16[k * 512 + n0];
                    float2 w0 = __bfloat1622float2(U.h2[0]);
                    float2 w1 = __bfloat1622float2(U.h2[1]);
                    acc0 = fmaf(hk, w0.x, acc0);
                    acc1 = fmaf(hk, w0.y, acc1);
                    acc2 = fmaf(hk, w1.x, acc2);
                    acc3 = fmaf(hk, w1.y, acc3);
                }
                sPart[ks * 512 + n0] = acc0;
                sPart[ks * 512 + n0 + 1] = acc1;
                sPart[ks * 512 + n0 + 2] = acc2;
                sPart[ks * 512 + n0 + 3] = acc3;
            }
            __syncthreads();
            if (tid < 512) {
                float s = bs[tid];
#pragma unroll
                for (int i = 0; i < 8; ++i) s += sPart[i * 512 + tid];
                sE[tid] = s;
            }
            __syncthreads();
            attn_body(bid, tid, sE, wos, ew, red, redv, sPart, bo);
        }
        grid_bar(target);
    }

    // tail: output for the last step (1 row per block)
    out_rows(bout, out, ML - 1, bid, 1, tid, sPart);
}

// --------------------------------- launcher --------------------------------------
extern "C" void kernel_launch(void* const* d_in, const int* in_sizes, int n_in,
                              void* d_out, int out_size) {
    (void)in_sizes; (void)n_in; (void)out_size;
    const float* x       = (const float*)d_in[0];
    const int*   targets = (const int*)  d_in[1];
    const float* emb     = (const float*)d_in[2];
    const float* Wi      = (const float*)d_in[3];
    const float* bi      = (const float*)d_in[4];
    const float* Ws      = (const float*)d_in[5];
    const float* bs      = (const float*)d_in[6];
    const float* wo      = (const float*)d_in[7];
    const float* bo      = (const float*)d_in[8];
    const float* W_ih    = (const float*)d_in[9];
    const float* W_hh    = (const float*)d_in[10];
    const float* b_ih    = (const float*)d_in[11];
    const float* b_hh    = (const float*)d_in[12];
    const float* Wout    = (const float*)d_in[13];
    const float* bout    = (const float*)d_in[14];
    float* out = (float*)d_out;

    __nv_bfloat16 *p_Wi16, *p_Ws16, *p_Wih16, *p_Whh16;
    cudaGetSymbolAddress((void**)&p_Wi16, g_Wi16);
    cudaGetSymbolAddress((void**)&p_Ws16, g_Ws16);
    cudaGetSymbolAddress((void**)&p_Wih16, g_Wih16);
    cudaGetSymbolAddress((void**)&p_Whh16, g_Whh16);

    static bool attr_set = false;
    if (!attr_set) {
        cudaFuncSetAttribute(xemb_wmma_kernel,
                             cudaFuncAttributeMaxDynamicSharedMemorySize, 81920);
        attr_set = true;
    }

    // one-time preprocessing
    init_kernel<<<128, 512>>>();
    convert_x_kernel<<<(BB * TT * LL) / 1024, 256>>>(x);
    f2bf_kernel<<<(LL * HH) / 1024, 256>>>(Wi, p_Wi16);
    f2bf_kernel<<<(HH * HH) / 1024, 256>>>(Ws, p_Ws16);
    f2bf_kernel<<<(1536 * 1024) / 1024, 256>>>(W_ih, p_Wih16);
    f2bf_kernel<<<(1536 * 512) / 1024, 256>>>(W_hh, p_Whh16);
    transpose_wout_kernel<<<CC, 512>>>(Wout);
    embseq_kernel<<<ML * BB, 128>>>(emb, targets);
    xemb_wmma_kernel<<<dim3(4, 256), 256, 81920>>>(bi);
    giemb_wmma_kernel<<<dim3(1536 / 64, ML * BB / 128), 256>>>();

    // the whole 26-step decode in ONE kernel
    persistent_kernel<<<128, 1024>>>(b_ih, b_hh, bout, wo, bo, bs, out);
}

// round 10
// speedup vs baseline: 1.1000x; 1.1000x over previous
#include <cuda_runtime.h>
#include <cuda_bf16.h>
#include <cuda_fp16.h>
#include <mma.h>
#include <math.h>

using namespace nvcuda;

#define BB 128
#define TT 256
#define LL 512
#define HH 512
#define CC 95
#define ML 26

// ---------------- device scratch (static: no runtime allocation) ----------------
__device__ __align__(16) __nv_bfloat16 g_x16[BB * TT * LL];     // 32 MB
__device__ __align__(16) __nv_bfloat16 g_xEmb16[BB * TT * HH];  // 32 MB
__device__ __align__(16) __nv_bfloat16 g_Wi16[LL * HH];
__device__ __align__(16) __nv_bfloat16 g_Ws16[HH * HH];
__device__ __align__(16) __nv_bfloat16 g_Wih16[1536 * 1024];
__device__ __align__(16) __nv_bfloat16 g_Whh16[1536 * 512];
__device__ __align__(16) __nv_bfloat16 g_embSeq[ML * BB * HH];
__device__ __align__(16) float g_giEmb[ML * BB * 1536];         // 20 MB
__device__ __align__(16) float g_WoutT[CC * HH];
__device__ __align__(16) float g_h[BB * HH];
__device__ __align__(16) float g_hHist[ML * BB * HH];           // 6.8 MB
__device__ __align__(16) __nv_bfloat16 g_h16[BB * HH];
__device__ __align__(16) __nv_bfloat16 g_ctx16[BB * HH];
__device__ __align__(16) float g_gates[BB * 3072];

// ---------------- fast math ------------------------------------------------------
__device__ __forceinline__ __half2 tanh2(__half2 x) {
    __half2 y;
    asm("tanh.approx.f16x2 %0, %1;"
        : "=r"(*(unsigned*)&y) : "r"(*(unsigned*)&x));
    return y;
}

__device__ __forceinline__ float fast_rcp_pos(float q) {
    float r = __uint_as_float(0x7EF127EAu - __float_as_uint(q));
    r = r * (2.0f - q * r);
    r = r * (2.0f - q * r);
    return r;
}

__device__ __forceinline__ float fast_tanh(float x) {  // accurate FMA-only (GRU n)
    float cx = fminf(fmaxf(x, -7.90531110763549805f), 7.90531110763549805f);
    float x2 = cx * cx;
    float p = fmaf(x2, -8.60467152213735e-11f, 5.12229709037114e-08f);
    p = fmaf(p, x2, 1.48572235717979e-05f);
    p = fmaf(p, x2, 6.37261928875436e-04f);
    p = fmaf(p, x2, 4.89352455891786e-03f);
    p = cx * p;
    float q = fmaf(x2, 1.19825839466702e-06f, 1.18534705686654e-04f);
    q = fmaf(q, x2, 2.26843463243900e-03f);
    q = fmaf(q, x2, 4.89352518554385e-03f);
    return p * fast_rcp_pos(q);
}

// ---------------- one-time helpers -----------------------------------------------
__global__ void init_kernel() {
    int i = blockIdx.x * 512 + threadIdx.x;
    g_h[i] = 0.f;
    g_h16[i] = __float2bfloat16(0.f);
}

__global__ void f2bf_kernel(const float* __restrict__ src,
                            __nv_bfloat16* __restrict__ dst) {
    int i = (blockIdx.x * 256 + threadIdx.x) * 4;
    float4 v = *(const float4*)(src + i);
    __nv_bfloat162* o = (__nv_bfloat162*)(dst + i);
    o[0] = __floats2bfloat162_rn(v.x, v.y);
    o[1] = __floats2bfloat162_rn(v.z, v.w);
}

__global__ void convert_x_kernel(const float* __restrict__ x) {
    int i = (blockIdx.x * 256 + threadIdx.x) * 4;
    float4 v = *(const float4*)(x + i);
    __nv_bfloat162* o = (__nv_bfloat162*)(g_x16 + i);
    o[0] = __floats2bfloat162_rn(v.x, v.y);
    o[1] = __floats2bfloat162_rn(v.z, v.w);
}

__global__ void transpose_wout_kernel(const float* __restrict__ Wout) {
    int c = blockIdx.x;
    int k = threadIdx.x;
    g_WoutT[c * HH + k] = Wout[k * CC + c];
}

__global__ void embseq_kernel(const float* __restrict__ emb,
                              const int* __restrict__ targets) {
    int m = blockIdx.x;  // 0..3327
    int step = m >> 7, b = m & 127;
    int y = (step == 0) ? CC : targets[b * ML + step - 1];
    int k = threadIdx.x * 4;
    float4 v = *(const float4*)(emb + y * HH + k);
    __nv_bfloat162* o = (__nv_bfloat162*)(g_embSeq + (size_t)m * HH + k);
    o[0] = __floats2bfloat162_rn(v.x, v.y);
    o[1] = __floats2bfloat162_rn(v.z, v.w);
}

// ---------------- one-time: xEmb = x @ Wi + bi (bf16 wmma, 128x128 tiles) --------
__global__ void xemb_wmma_kernel(const float* __restrict__ bias) {
    extern __shared__ char dyn[];
    __nv_bfloat16 (*As)[32] = (__nv_bfloat16(*)[32])dyn;
    __nv_bfloat16 (*Bs)[128] = (__nv_bfloat16(*)[128])(dyn + 8192);
    float (*Co)[128] = (float(*)[128])(dyn + 16384);
    const int tid = threadIdx.x;
    const int wid = tid >> 5;
    const int m0 = blockIdx.y * 128;
    const int n0 = blockIdx.x * 128;
    const int warpM = wid & 3;
    const int warpN = wid >> 2;

    wmma::fragment<wmma::accumulator, 16, 16, 16, float> c[2][4];
#pragma unroll
    for (int i = 0; i < 2; ++i)
#pragma unroll
        for (int j = 0; j < 4; ++j) wmma::fill_fragment(c[i][j], 0.f);

    for (int k0 = 0; k0 < 512; k0 += 32) {
#pragma unroll
        for (int i = 0; i < 2; ++i) {
            int idx = tid + i * 256;
            int m = idx >> 2, kq = idx & 3;
            *(uint4*)&As[m][kq * 8] =
                *(const uint4*)&g_x16[(size_t)(m0 + m) * 512 + k0 + kq * 8];
        }
#pragma unroll
        for (int i = 0; i < 2; ++i) {
            int idx = tid + i * 256;
            int k = idx >> 4, q = idx & 15;
            *(uint4*)&Bs[k][q * 8] =
                *(const uint4*)&g_Wi16[(size_t)(k0 + k) * 512 + n0 + q * 8];
        }
        __syncthreads();
#pragma unroll
        for (int kk = 0; kk < 32; kk += 16) {
            wmma::fragment<wmma::matrix_a, 16, 16, 16, __nv_bfloat16, wmma::row_major> a[2];
            wmma::fragment<wmma::matrix_b, 16, 16, 16, __nv_bfloat16, wmma::row_major> b[4];
#pragma unroll
            for (int i = 0; i < 2; ++i)
                wmma::load_matrix_sync(a[i], &As[warpM * 32 + i * 16][kk], 32);
#pragma unroll
            for (int j = 0; j < 4; ++j)
                wmma::load_matrix_sync(b[j], &Bs[kk][warpN * 64 + j * 16], 128);
#pragma unroll
            for (int i = 0; i < 2; ++i)
#pragma unroll
                for (int j = 0; j < 4; ++j)
                    wmma::mma_sync(c[i][j], a[i], b[j], c[i][j]);
        }
        __syncthreads();
    }
#pragma unroll
    for (int i = 0; i < 2; ++i)
#pragma unroll
        for (int j = 0; j < 4; ++j)
            wmma::store_matrix_sync(&Co[warpM * 32 + i * 16][warpN * 64 + j * 16],
                                    c[i][j], 128, wmma::mem_row_major);
    __syncthreads();
#pragma unroll
    for (int it = 0; it < 64; ++it) {
        int idx = it * 256 + tid;
        int m = idx >> 7, cc = idx & 127;
        g_xEmb16[(size_t)(m0 + m) * 512 + n0 + cc] =
            __float2bfloat16(Co[m][cc] + bias[n0 + cc]);
    }
}

// ------ one-time: giEmb = embSeq @ W_ih[:, :512]^T  [3328,1536] fp32 -------------
__global__ void giemb_wmma_kernel() {
    __shared__ __nv_bfloat16 As[128][32];
    __shared__ __nv_bfloat16 Bs[64][32];
    const int tid = threadIdx.x;
    const int wid = tid >> 5;
    const int m0 = blockIdx.y * 128;
    const int n0 = blockIdx.x * 64;

    wmma::fragment<wmma::accumulator, 16, 16, 16, float> c[4];
#pragma unroll
    for (int j = 0; j < 4; ++j) wmma::fill_fragment(c[j], 0.f);

    for (int k0 = 0; k0 < 512; k0 += 32) {
#pragma unroll
        for (int i = 0; i < 2; ++i) {
            int idx = tid + i * 256;
            int m = idx >> 2, kq = idx & 3;
            *(uint4*)&As[m][kq * 8] =
                *(const uint4*)&g_embSeq[(size_t)(m0 + m) * 512 + k0 + kq * 8];
        }
        {
            int j = tid >> 2, kq = tid & 3;
            *(uint4*)&Bs[j][kq * 8] =
                *(const uint4*)&g_Wih16[(size_t)(n0 + j) * 1024 + k0 + kq * 8];
        }
        __syncthreads();
#pragma unroll
        for (int kk = 0; kk < 32; kk += 16) {
            wmma::fragment<wmma::matrix_a, 16, 16, 16, __nv_bfloat16, wmma::row_major> a;
            wmma::load_matrix_sync(a, &As[wid * 16][kk], 32);
#pragma unroll
            for (int j = 0; j < 4; ++j) {
                wmma::fragment<wmma::matrix_b, 16, 16, 16, __nv_bfloat16, wmma::col_major> bf;
                wmma::load_matrix_sync(bf, &Bs[j * 16][kk], 32);
                wmma::mma_sync(c[j], a, bf, c[j]);
            }
        }
        __syncthreads();
    }
#pragma unroll
    for (int j = 0; j < 4; ++j)
        wmma::store_matrix_sync(&g_giEmb[(size_t)(m0 + wid * 16) * 1536 + n0 + j * 16],
                                c[j], 1536, wmma::mem_row_major);
}

// ---------------- attention body (f16x2 MUFU tanh) -------------------------------
__device__ __forceinline__ void attn_body(int b, int tid,
                                          const float* sE, const float* wos,
                                          float* ew, float* red, float* redv,
                                          float* sPart, const float* bo) {
    {
        const int t = tid >> 2, q = tid & 3;
        const __nv_bfloat16* row =
            g_xEmb16 + ((size_t)(b * 256 + t)) * 512 + q * 128;
        float acc = 0.f;
#pragma unroll
        for (int i = 0; i < 16; ++i) {
            union { uint4 u; __nv_bfloat162 h2[4]; } U;
            U.u = *(const uint4*)&row[i * 8];
            int base = q * 128 + i * 8;
#pragma unroll
            for (int j = 0; j < 4; ++j) {
                float2 v = __bfloat1622float2(U.h2[j]);
                int idx = base + 2 * j;
                __half2 a2 = __floats2half2_rn(v.x + sE[idx], v.y + sE[idx + 1]);
                float2 tf = __half22float2(tanh2(a2));
                acc = fmaf(wos[idx], tf.x, acc);
                acc = fmaf(wos[idx + 1], tf.y, acc);
            }
        }
        acc += __shfl_xor_sync(0xffffffffu, acc, 1);
        acc += __shfl_xor_sync(0xffffffffu, acc, 2);
        if (q == 0) ew[t] = acc + bo[0];
    }
    __syncthreads();

    if (tid < 256) {
        float v = ew[tid];
        float m = v;
#pragma unroll
        for (int off = 16; off > 0; off >>= 1)
            m = fmaxf(m, __shfl_xor_sync(0xffffffffu, m, off));
        if ((tid & 31) == 0) red[tid >> 5] = m;
    }
    __syncthreads();
    if (tid == 0) {
        float m = red[0];
#pragma unroll
        for (int w = 1; w < 8; ++w) m = fmaxf(m, red[w]);
        redv[0] = m;
    }
    __syncthreads();
    if (tid < 256) {
        float p = __expf(ew[tid] - redv[0]);
        ew[tid] = p;
        float s = p;
#pragma unroll
        for (int off = 16; off > 0; off >>= 1)
            s += __shfl_xor_sync(0xffffffffu, s, off);
        if ((tid & 31) == 0) red[8 + (tid >> 5)] = s;
    }
    __syncthreads();
    if (tid == 0) {
        float s = 0.f;
#pragma unroll
        for (int w = 0; w < 8; ++w) s += red[8 + w];
        redv[1] = 1.0f / s;
    }
    __syncthreads();
    if (tid < 256) ew[tid] *= redv[1];
    __syncthreads();

    {
        const int d2 = tid & 255, tq = tid >> 8;
        const __nv_bfloat162* xb =
            (const __nv_bfloat162*)g_x16 + ((size_t)b * 256 + tq * 64) * 256 + d2;
        float ax = 0.f, ay = 0.f;
#pragma unroll 8
        for (int tt = 0; tt < 64; ++tt) {
            float a = ew[tq * 64 + tt];
            float2 v = __bfloat1622float2(xb[(size_t)tt * 256]);
            ax = fmaf(a, v.x, ax);
            ay = fmaf(a, v.y, ay);
        }
        sPart[tq * 512 + 2 * d2] = ax;
        sPart[tq * 512 + 2 * d2 + 1] = ay;
    }
    __syncthreads();
    if (tid < 512) {
        float c = sPart[tid] + sPart[512 + tid] + sPart[1024 + tid] + sPart[1536 + tid];
        g_ctx16[b * 512 + tid] = __float2bfloat16(c);
    }
}

// ---------------- step 0 attention (h = 0 -> sEmb = bs) --------------------------
__global__ void attn0_kernel(const float* __restrict__ wo,
                             const float* __restrict__ bo,
                             const float* __restrict__ bs) {
    const int b = blockIdx.x;
    const int tid = threadIdx.x;
    __shared__ float sE[512], wos[512], ew[256], red[16], redv[2];
    __shared__ float sPart[4 * 512];
    if (tid < 512) {
        sE[tid] = bs[tid];
        wos[tid] = wo[tid];
    }
    __syncthreads();
    attn_body(b, tid, sE, wos, ew, red, redv, sPart, bo);
}

// ---------- per-step gates GEMM (BK=64): [ctx@Wc^T + giEmb | h@Whh^T] ------------
// grid 96 (48 gi + 48 gh), 256 threads
__global__ void gates_kernel(int step) {
    __shared__ __nv_bfloat16 As[128][64];   // 16 KB
    __shared__ __nv_bfloat16 Bs[32][64];    // 4 KB
    const int tid = threadIdx.x;
    const int wid = tid >> 5;
    const bool hh = blockIdx.x >= 48;
    const __nv_bfloat16* A = hh ? g_h16 : g_ctx16;
    const __nv_bfloat16* W = hh ? g_Whh16 : g_Wih16;
    const int ldw = hh ? 512 : 1024;
    const int koff = hh ? 0 : 512;
    const int n0 = (hh ? blockIdx.x - 48 : blockIdx.x) * 32;
    const int outc = (hh ? 1536 : 0) + n0;

    wmma::fragment<wmma::accumulator, 16, 16, 16, float> c[2];
    if (hh) {
        wmma::fill_fragment(c[0], 0.f);
        wmma::fill_fragment(c[1], 0.f);
    } else {
        const float* gi = g_giEmb + ((size_t)step * 128 + wid * 16) * 1536 + n0;
        wmma::load_matrix_sync(c[0], gi, 1536, wmma::mem_row_major);
        wmma::load_matrix_sync(c[1], gi + 16, 1536, wmma::mem_row_major);
    }

    for (int k0 = 0; k0 < 512; k0 += 64) {
#pragma unroll
        for (int i = 0; i < 4; ++i) {
            int idx = tid + i * 256;       // 0..1023 uint4 slots
            int m = idx >> 3, q = idx & 7;
            *(uint4*)&As[m][q * 8] =
                *(const uint4*)&A[(size_t)m * 512 + k0 + q * 8];
        }
        {
            int j = tid >> 3, q = tid & 7;  // 32 rows x 8 quads
            *(uint4*)&Bs[j][q * 8] =
                *(const uint4*)&W[(size_t)(n0 + j) * ldw + koff + k0 + q * 8];
        }
        __syncthreads();
#pragma unroll
        for (int kk = 0; kk < 64; kk += 16) {
            wmma::fragment<wmma::matrix_a, 16, 16, 16, __nv_bfloat16, wmma::row_major> a;
            wmma::load_matrix_sync(a, &As[wid * 16][kk], 64);
#pragma unroll
            for (int j = 0; j < 2; ++j) {
                wmma::fragment<wmma::matrix_b, 16, 16, 16, __nv_bfloat16, wmma::col_major> bf;
                wmma::load_matrix_sync(bf, &Bs[j * 16][kk], 64);
                wmma::mma_sync(c[j], a, bf, c[j]);
            }
        }
        __syncthreads();
    }
#pragma unroll
    for (int j = 0; j < 2; ++j)
        wmma::store_matrix_sync(&g_gates[(size_t)(wid * 16) * 3072 + outc + j * 16],
                                c[j], 3072, wmma::mem_row_major);
}

// ------ fused: GRU pointwise + h store + sEmb + attention ------------------------
// grid 128, 1024 threads
__global__ void fused_kernel(const float* __restrict__ b_ih,
                             const float* __restrict__ b_hh,
                             const float* __restrict__ wo,
                             const float* __restrict__ bo,
                             const float* __restrict__ bs,
                             int step) {
    const int b = blockIdx.x;
    const int tid = threadIdx.x;
    __shared__ float hs[512], sE[512], wos[512], ew[256];
    __shared__ float red[16], redv[2];
    __shared__ float sPart[8 * 512];

    // ---- GRU pointwise update ----
    if (tid < 512) {
        const float* g = g_gates + b * 3072;
        float gir = g[tid] + b_ih[tid];
        float giz = g[tid + 512] + b_ih[tid + 512];
        float gin = g[tid + 1024] + b_ih[tid + 1024];
        float ghr = g[tid + 1536] + b_hh[tid];
        float ghz = g[tid + 2048] + b_hh[tid + 512];
        float ghn = g[tid + 2560] + b_hh[tid + 1024];
        float r = 1.f / (1.f + __expf(-(gir + ghr)));
        float z = 1.f / (1.f + __expf(-(giz + ghz)));
        float n = fast_tanh(gin + r * ghn);
        float hv = (1.f - z) * n + z * g_h[b * 512 + tid];
        g_h[b * 512 + tid] = hv;
        g_hHist[((size_t)step * BB + b) * 512 + tid] = hv;
        g_h16[b * 512 + tid] = __float2bfloat16(hv);
        hs[tid] = hv;
        wos[tid] = wo[tid];
    }
    __syncthreads();

    if (step == ML - 1) return;

    // ---- sEmb = h @ Ws + bs (8-way k-split over 1024 threads) ----
    {
        const int ks = tid >> 7;
        const int n0 = (tid & 127) * 4;
        float acc0 = 0.f, acc1 = 0.f, acc2 = 0.f, acc3 = 0.f;
#pragma unroll 4
        for (int kk = 0; kk < 64; ++kk) {
            int k = ks * 64 + kk;
            float hk = hs[k];
            union { uint2 u; __nv_bfloat162 h2[2]; } U;
            U.u = *(const uint2*)&g_Ws16[k * 512 + n0];
            float2 w0 = __bfloat1622float2(U.h2[0]);
            float2 w1 = __bfloat1622float2(U.h2[1]);
            acc0 = fmaf(hk, w0.x, acc0);
            acc1 = fmaf(hk, w0.y, acc1);
            acc2 = fmaf(hk, w1.x, acc2);
            acc3 = fmaf(hk, w1.y, acc3);
        }
        sPart[ks * 512 + n0] = acc0;
        sPart[ks * 512 + n0 + 1] = acc1;
        sPart[ks * 512 + n0 + 2] = acc2;
        sPart[ks * 512 + n0 + 3] = acc3;
    }
    __syncthreads();
    if (tid < 512) {
        float s = bs[tid];
#pragma unroll
        for (int i = 0; i < 8; ++i) s += sPart[i * 512 + tid];
        sE[tid] = s;
    }
    __syncthreads();

    attn_body(b, tid, sE, wos, ew, red, redv, sPart, bo);
}

// ------ final: logits + log-softmax for all 3328 rows ----------------------------
// grid 416 blocks, 512 threads, 8 rows per block
__global__ void out_final_kernel(const float* __restrict__ bout,
                                 float* __restrict__ out) {
    const int m0 = blockIdx.x * 8;
    const int tid = threadIdx.x;
    __shared__ float hs8[8][512];
    __shared__ float lg[8][96];

    for (int i = tid; i < 8 * 512; i += 512)
        hs8[i >> 9][i & 511] = g_hHist[(size_t)m0 * 512 + i];
    __syncthreads();

    for (int i = tid; i < 8 * CC; i += 512) {
        int r = i / CC, c = i % CC;
        const float4* wp = (const float4*)(g_WoutT + c * 512);
        const float4* hp = (const float4*)hs8[r];
        float acc = 0.f;
#pragma unroll 16
        for (int k = 0; k < 128; ++k) {
            float4 h4 = hp[k], w4 = wp[k];
            acc = fmaf(h4.x, w4.x, acc);
            acc = fmaf(h4.y, w4.y, acc);
            acc = fmaf(h4.z, w4.z, acc);
            acc = fmaf(h4.w, w4.w, acc);
        }
        lg[r][c] = acc + bout[c];
    }
    __syncthreads();

    const int warp = tid >> 5, lane = tid & 31;
    if (warp < 8) {
        float v0 = (lane < CC) ? lg[warp][lane] : -1e30f;
        float v1 = (lane + 32 < CC) ? lg[warp][lane + 32] : -1e30f;
        float v2 = (lane + 64 < CC) ? lg[warp][lane + 64] : -1e30f;
        float m = fmaxf(v0, fmaxf(v1, v2));
#pragma unroll
        for (int off = 16; off > 0; off >>= 1)
            m = fmaxf(m, __shfl_xor_sync(0xffffffffu, m, off));
        float s = ((lane < CC) ? __expf(v0 - m) : 0.f) +
                  ((lane + 32 < CC) ? __expf(v1 - m) : 0.f) +
                  ((lane + 64 < CC) ? __expf(v2 - m) : 0.f);
#pragma unroll
        for (int off = 16; off > 0; off >>= 1)
            s += __shfl_xor_sync(0xffffffffu, s, off);
        float lse = m + logf(s);
        float* o = out + (size_t)(m0 + warp) * CC;
        if (lane < CC) o[lane] = v0 - lse;
        if (lane + 32 < CC) o[lane + 32] = v1 - lse;
        if (lane + 64 < CC) o[lane + 64] = v2 - lse;
    }
}

// --------------------------------- launcher --------------------------------------
extern "C" void kernel_launch(void* const* d_in, const int* in_sizes, int n_in,
                              void* d_out, int out_size) {
    (void)in_sizes; (void)n_in; (void)out_size;
    const float* x       = (const float*)d_in[0];
    const int*   targets = (const int*)  d_in[1];
    const float* emb     = (const float*)d_in[2];
    const float* Wi      = (const float*)d_in[3];
    const float* bi      = (const float*)d_in[4];
    const float* Ws      = (const float*)d_in[5];
    const float* bs      = (const float*)d_in[6];
    const float* wo      = (const float*)d_in[7];
    const float* bo      = (const float*)d_in[8];
    const float* W_ih    = (const float*)d_in[9];
    const float* W_hh    = (const float*)d_in[10];
    const float* b_ih    = (const float*)d_in[11];
    const float* b_hh    = (const float*)d_in[12];
    const float* Wout    = (const float*)d_in[13];
    const float* bout    = (const float*)d_in[14];
    float* out = (float*)d_out;

    __nv_bfloat16 *p_Wi16, *p_Ws16, *p_Wih16, *p_Whh16;
    cudaGetSymbolAddress((void**)&p_Wi16, g_Wi16);
    cudaGetSymbolAddress((void**)&p_Ws16, g_Ws16);
    cudaGetSymbolAddress((void**)&p_Wih16, g_Wih16);
    cudaGetSymbolAddress((void**)&p_Whh16, g_Whh16);

    static bool attr_set = false;
    if (!attr_set) {
        cudaFuncSetAttribute(xemb_wmma_kernel,
                             cudaFuncAttributeMaxDynamicSharedMemorySize, 81920);
        attr_set = true;
    }

    // one-time preprocessing
    init_kernel<<<128, 512>>>();
    convert_x_kernel<<<(BB * TT * LL) / 1024, 256>>>(x);
    f2bf_kernel<<<(LL * HH) / 1024, 256>>>(Wi, p_Wi16);
    f2bf_kernel<<<(HH * HH) / 1024, 256>>>(Ws, p_Ws16);
    f2bf_kernel<<<(1536 * 1024) / 1024, 256>>>(W_ih, p_Wih16);
    f2bf_kernel<<<(1536 * 512) / 1024, 256>>>(W_hh, p_Whh16);
    transpose_wout_kernel<<<CC, 512>>>(Wout);
    embseq_kernel<<<ML * BB, 128>>>(emb, targets);
    xemb_wmma_kernel<<<dim3(4, 256), 256, 81920>>>(bi);
    giemb_wmma_kernel<<<dim3(1536 / 64, ML * BB / 128), 256>>>();

    // step 0 attention (h = 0)
    attn0_kernel<<<BB, 1024>>>(wo, bo, bs);

    for (int step = 0; step < ML; ++step) {
        gates_kernel<<<96, 256>>>(step);
        fused_kernel<<<BB, 1024>>>(b_ih, b_hh, wo, bo, bs, step);
    }

    // all outputs at once (off the critical path)
    out_final_kernel<<<ML * BB / 8, 512>>>(bout, out);
}

// round 13
// speedup vs baseline: 1.1199x; 1.0181x over previous
#include <cuda_runtime.h>
#include <cuda_bf16.h>
#include <cuda_fp16.h>
#include <mma.h>
#include <math.h>

using namespace nvcuda;

#define BB 128
#define TT 256
#define LL 512
#define HH 512
#define CC 95
#define ML 26

// ---------------- device scratch (static: no runtime allocation) ----------------
__device__ __align__(16) __nv_bfloat16 g_x16[BB * TT * LL];     // 32 MB
__device__ __align__(16) __nv_bfloat16 g_xEmb16[BB * TT * HH];  // 32 MB
__device__ __align__(16) __nv_bfloat16 g_Wi16[LL * HH];
__device__ __align__(16) __nv_bfloat16 g_Ws16[HH * HH];
__device__ __align__(16) __nv_bfloat16 g_Wih16[1536 * 1024];
__device__ __align__(16) __nv_bfloat16 g_Whh16[1536 * 512];
__device__ __align__(16) __nv_bfloat16 g_embSeq[ML * BB * HH];
__device__ __align__(16) float g_giEmb[ML * BB * 1536];         // 20 MB
__device__ __align__(16) float g_WoutT[CC * HH];
__device__ __align__(16) float g_hHist[ML * BB * HH];           // 6.8 MB
__device__ __align__(16) __nv_bfloat16 g_h16[BB * HH];
__device__ __align__(16) __nv_bfloat16 g_ctx16[BB * HH];
__device__ __align__(16) float g_gates[BB * 3072];

// ---------------- PDL intrinsics -------------------------------------------------
__device__ __forceinline__ void gdc_wait() {
    asm volatile("griddepcontrol.wait;" ::: "memory");
}
__device__ __forceinline__ void gdc_launch() {
    asm volatile("griddepcontrol.launch_dependents;" ::: "memory");
}

// ---------------- fast math ------------------------------------------------------
__device__ __forceinline__ __half2 tanh2(__half2 x) {
    __half2 y;
    asm("tanh.approx.f16x2 %0, %1;"
        : "=r"(*(unsigned*)&y) : "r"(*(unsigned*)&x));
    return y;
}

__device__ __forceinline__ float fast_rcp_pos(float q) {
    float r = __uint_as_float(0x7EF127EAu - __float_as_uint(q));
    r = r * (2.0f - q * r);
    r = r * (2.0f - q * r);
    return r;
}

__device__ __forceinline__ float fast_tanh(float x) {  // accurate FMA-only (GRU n)
    float cx = fminf(fmaxf(x, -7.90531110763549805f), 7.90531110763549805f);
    float x2 = cx * cx;
    float p = fmaf(x2, -8.60467152213735e-11f, 5.12229709037114e-08f);
    p = fmaf(p, x2, 1.48572235717979e-05f);
    p = fmaf(p, x2, 6.37261928875436e-04f);
    p = fmaf(p, x2, 4.89352455891786e-03f);
    p = cx * p;
    float q = fmaf(x2, 1.19825839466702e-06f, 1.18534705686654e-04f);
    q = fmaf(q, x2, 2.26843463243900e-03f);
    q = fmaf(q, x2, 4.89352518554385e-03f);
    return p * fast_rcp_pos(q);
}

// ---------------- ONE merged prep kernel (all one-time conversions) --------------
__device__ __forceinline__ void cvt4(const float* __restrict__ src,
                                     __nv_bfloat16* __restrict__ dst, int i) {
    float4 v = *(const float4*)(src + i);
    __nv_bfloat162* o = (__nv_bfloat162*)(dst + i);
    o[0] = __floats2bfloat162_rn(v.x, v.y);
    o[1] = __floats2bfloat162_rn(v.z, v.w);
}

__global__ void prep_kernel(const float* __restrict__ x,
                            const float* __restrict__ Wi,
                            const float* __restrict__ Ws,
                            const float* __restrict__ W_ih,
                            const float* __restrict__ W_hh,
                            const float* __restrict__ Wout,
                            const float* __restrict__ emb,
                            const int* __restrict__ targets) {
    const int blk = blockIdx.x;
    const int tid = threadIdx.x;
    if (blk < 16384) {                       // x -> bf16
        cvt4(x, g_x16, blk * 1024 + tid * 4);
    } else if (blk < 16640) {                // Wi
        cvt4(Wi, g_Wi16, (blk - 16384) * 1024 + tid * 4);
    } else if (blk < 16896) {                // Ws
        cvt4(Ws, g_Ws16, (blk - 16640) * 1024 + tid * 4);
    } else if (blk < 18432) {                // W_ih
        cvt4(W_ih, g_Wih16, (blk - 16896) * 1024 + tid * 4);
    } else if (blk < 19200) {                // W_hh
        cvt4(W_hh, g_Whh16, (blk - 18432) * 1024 + tid * 4);
    } else if (blk < 19295) {                // Wout transpose
        int c = blk - 19200;
        g_WoutT[c * HH + tid] = Wout[tid * CC + c];
        g_WoutT[c * HH + tid + 256] = Wout[(tid + 256) * CC + c];
    } else if (blk < 20959) {                // teacher-forced emb gather (bf16)
        int e = (blk - 19295) * 1024 + tid * 4;
        int m = e >> 9, k = e & 511;
        int step = m >> 7, b = m & 127;
        int y = (step == 0) ? CC : targets[b * ML + step - 1];
        float4 v = *(const float4*)(emb + y * HH + k);
        __nv_bfloat162* o = (__nv_bfloat162*)(g_embSeq + (size_t)m * HH + k);
        o[0] = __floats2bfloat162_rn(v.x, v.y);
        o[1] = __floats2bfloat162_rn(v.z, v.w);
    } else {                                 // h16 = 0
        int i = (blk - 20959) * 1024 + tid * 4;
        __nv_bfloat162 z = __floats2bfloat162_rn(0.f, 0.f);
        __nv_bfloat162* o = (__nv_bfloat162*)(g_h16 + i);
        o[0] = z;
        o[1] = z;
    }
}

// ---------------- one-time: xEmb = x @ Wi + bi (bf16 wmma, 128x128 tiles) --------
__global__ void xemb_wmma_kernel(const float* __restrict__ bias) {
    extern __shared__ char dyn[];
    __nv_bfloat16 (*As)[32] = (__nv_bfloat16(*)[32])dyn;
    __nv_bfloat16 (*Bs)[128] = (__nv_bfloat16(*)[128])(dyn + 8192);
    float (*Co)[128] = (float(*)[128])(dyn + 16384);
    const int tid = threadIdx.x;
    const int wid = tid >> 5;
    const int m0 = blockIdx.y * 128;
    const int n0 = blockIdx.x * 128;
    const int warpM = wid & 3;
    const int warpN = wid >> 2;

    wmma::fragment<wmma::accumulator, 16, 16, 16, float> c[2][4];
#pragma unroll
    for (int i = 0; i < 2; ++i)
#pragma unroll
        for (int j = 0; j < 4; ++j) wmma::fill_fragment(c[i][j], 0.f);

    for (int k0 = 0; k0 < 512; k0 += 32) {
#pragma unroll
        for (int i = 0; i < 2; ++i) {
            int idx = tid + i * 256;
            int m = idx >> 2, kq = idx & 3;
            *(uint4*)&As[m][kq * 8] =
                *(const uint4*)&g_x16[(size_t)(m0 + m) * 512 + k0 + kq * 8];
        }
#pragma unroll
        for (int i = 0; i < 2; ++i) {
            int idx = tid + i * 256;
            int k = idx >> 4, q = idx & 15;
            *(uint4*)&Bs[k][q * 8] =
                *(const uint4*)&g_Wi16[(size_t)(k0 + k) * 512 + n0 + q * 8];
        }
        __syncthreads();
#pragma unroll
        for (int kk = 0; kk < 32; kk += 16) {
            wmma::fragment<wmma::matrix_a, 16, 16, 16, __nv_bfloat16, wmma::row_major> a[2];
            wmma::fragment<wmma::matrix_b, 16, 16, 16, __nv_bfloat16, wmma::row_major> b[4];
#pragma unroll
            for (int i = 0; i < 2; ++i)
                wmma::load_matrix_sync(a[i], &As[warpM * 32 + i * 16][kk], 32);
#pragma unroll
            for (int j = 0; j < 4; ++j)
                wmma::load_matrix_sync(b[j], &Bs[kk][warpN * 64 + j * 16], 128);
#pragma unroll
            for (int i = 0; i < 2; ++i)
#pragma unroll
                for (int j = 0; j < 4; ++j)
                    wmma::mma_sync(c[i][j], a[i], b[j], c[i][j]);
        }
        __syncthreads();
    }
#pragma unroll
    for (int i = 0; i < 2; ++i)
#pragma unroll
        for (int j = 0; j < 4; ++j)
            wmma::store_matrix_sync(&Co[warpM * 32 + i * 16][warpN * 64 + j * 16],
                                    c[i][j], 128, wmma::mem_row_major);
    __syncthreads();
#pragma unroll
    for (int it = 0; it < 64; ++it) {
        int idx = it * 256 + tid;
        int m = idx >> 7, cc = idx & 127;
        g_xEmb16[(size_t)(m0 + m) * 512 + n0 + cc] =
            __float2bfloat16(Co[m][cc] + bias[n0 + cc]);
    }
}

// ------ one-time: giEmb = embSeq @ W_ih[:, :512]^T  [3328,1536] fp32 -------------
__global__ void giemb_wmma_kernel() {
    __shared__ __nv_bfloat16 As[128][32];
    __shared__ __nv_bfloat16 Bs[64][32];
    const int tid = threadIdx.x;
    const int wid = tid >> 5;
    const int m0 = blockIdx.y * 128;
    const int n0 = blockIdx.x * 64;

    wmma::fragment<wmma::accumulator, 16, 16, 16, float> c[4];
#pragma unroll
    for (int j = 0; j < 4; ++j) wmma::fill_fragment(c[j], 0.f);

    for (int k0 = 0; k0 < 512; k0 += 32) {
#pragma unroll
        for (int i = 0; i < 2; ++i) {
            int idx = tid + i * 256;
            int m = idx >> 2, kq = idx & 3;
            *(uint4*)&As[m][kq * 8] =
                *(const uint4*)&g_embSeq[(size_t)(m0 + m) * 512 + k0 + kq * 8];
        }
        {
            int j = tid >> 2, kq = tid & 3;
            *(uint4*)&Bs[j][kq * 8] =
                *(const uint4*)&g_Wih16[(size_t)(n0 + j) * 1024 + k0 + kq * 8];
        }
        __syncthreads();
#pragma unroll
        for (int kk = 0; kk < 32; kk += 16) {
            wmma::fragment<wmma::matrix_a, 16, 16, 16, __nv_bfloat16, wmma::row_major> a;
            wmma::load_matrix_sync(a, &As[wid * 16][kk], 32);
#pragma unroll
            for (int j = 0; j < 4; ++j) {
                wmma::fragment<wmma::matrix_b, 16, 16, 16, __nv_bfloat16, wmma::col_major> bf;
                wmma::load_matrix_sync(bf, &Bs[j * 16][kk], 32);
                wmma::mma_sync(c[j], a, bf, c[j]);
            }
        }
        __syncthreads();
    }
#pragma unroll
    for (int j = 0; j < 4; ++j)
        wmma::store_matrix_sync(&g_giEmb[(size_t)(m0 + wid * 16) * 1536 + n0 + j * 16],
                                c[j], 1536, wmma::mem_row_major);
}

// ---------------- attention body (f16x2 MUFU tanh) -------------------------------
__device__ __forceinline__ void attn_body(int b, int tid,
                                          const float* sE, const float* wos,
                                          float* ew, float* red, float* redv,
                                          float* sPart, const float* bo) {
    {
        const int t = tid >> 2, q = tid & 3;
        const __nv_bfloat16* row =
            g_xEmb16 + ((size_t)(b * 256 + t)) * 512 + q * 128;
        float acc = 0.f;
#pragma unroll
        for (int i = 0; i < 16; ++i) {
            union { uint4 u; __nv_bfloat162 h2[4]; } U;
            U.u = *(const uint4*)&row[i * 8];
            int base = q * 128 + i * 8;
#pragma unroll
            for (int j = 0; j < 4; ++j) {
                float2 v = __bfloat1622float2(U.h2[j]);
                int idx = base + 2 * j;
                __half2 a2 = __floats2half2_rn(v.x + sE[idx], v.y + sE[idx + 1]);
                float2 tf = __half22float2(tanh2(a2));
                acc = fmaf(wos[idx], tf.x, acc);
                acc = fmaf(wos[idx + 1], tf.y, acc);
            }
        }
        acc += __shfl_xor_sync(0xffffffffu, acc, 1);
        acc += __shfl_xor_sync(0xffffffffu, acc, 2);
        if (q == 0) ew[t] = acc + bo[0];
    }
    __syncthreads();

    if (tid < 256) {
        float v = ew[tid];
        float m = v;
#pragma unroll
        for (int off = 16; off > 0; off >>= 1)
            m = fmaxf(m, __shfl_xor_sync(0xffffffffu, m, off));
        if ((tid & 31) == 0) red[tid >> 5] = m;
    }
    __syncthreads();
    if (tid == 0) {
        float m = red[0];
#pragma unroll
        for (int w = 1; w < 8; ++w) m = fmaxf(m, red[w]);
        redv[0] = m;
    }
    __syncthreads();
    if (tid < 256) {
        float p = __expf(ew[tid] - redv[0]);
        ew[tid] = p;
        float s = p;
#pragma unroll
        for (int off = 16; off > 0; off >>= 1)
            s += __shfl_xor_sync(0xffffffffu, s, off);
        if ((tid & 31) == 0) red[8 + (tid >> 5)] = s;
    }
    __syncthreads();
    if (tid == 0) {
        float s = 0.f;
#pragma unroll
        for (int w = 0; w < 8; ++w) s += red[8 + w];
        redv[1] = 1.0f / s;
    }
    __syncthreads();
    if (tid < 256) ew[tid] *= redv[1];
    __syncthreads();

    {
        const int d2 = tid & 255, tq = tid >> 8;
        const __nv_bfloat162* xb =
            (const __nv_bfloat162*)g_x16 + ((size_t)b * 256 + tq * 64) * 256 + d2;
        float ax = 0.f, ay = 0.f;
#pragma unroll 8
        for (int tt = 0; tt < 64; ++tt) {
            float a = ew[tq * 64 + tt];
            float2 v = __bfloat1622float2(xb[(size_t)tt * 256]);
            ax = fmaf(a, v.x, ax);
            ay = fmaf(a, v.y, ay);
        }
        sPart[tq * 512 + 2 * d2] = ax;
        sPart[tq * 512 + 2 * d2 + 1] = ay;
    }
    __syncthreads();
    if (tid < 512) {
        float c = sPart[tid] + sPart[512 + tid] + sPart[1024 + tid] + sPart[1536 + tid];
        g_ctx16[b * 512 + tid] = __float2bfloat16(c);
    }
}

// ---------------- step 0 attention (h = 0 -> sEmb = bs) --------------------------
__global__ void attn0_kernel(const float* __restrict__ wo,
                             const float* __restrict__ bo,
                             const float* __restrict__ bs) {
    const int b = blockIdx.x;
    const int tid = threadIdx.x;
    __shared__ float sE[512], wos[512], ew[256], red[16], redv[2];
    __shared__ float sPart[4 * 512];
    if (tid < 512) {
        sE[tid] = bs[tid];
        wos[tid] = wo[tid];
    }
    __syncthreads();
    attn_body(b, tid, sE, wos, ew, red, redv, sPart, bo);
}

// ---------- per-step gates GEMM: PDL + full-tile smem staging --------------------
// grid 96 (48 gi + 48 gh), 256 threads. dyn smem: A 128x512 (128KB) + B 32x512 (32KB)
__global__ void gates_kernel(int step) {
    extern __shared__ char dyn[];
    __nv_bfloat16 (*As)[512] = (__nv_bfloat16(*)[512])dyn;
    __nv_bfloat16 (*Ball)[512] = (__nv_bfloat16(*)[512])(dyn + 131072);
    const int tid = threadIdx.x;
    const int wid = tid >> 5;
    const bool hh = blockIdx.x >= 48;
    const __nv_bfloat16* A = hh ? g_h16 : g_ctx16;
    const __nv_bfloat16* W = hh ? g_Whh16 : g_Wih16;
    const int ldw = hh ? 512 : 1024;
    const int koff = hh ? 0 : 512;
    const int n0 = (hh ? blockIdx.x - 48 : blockIdx.x) * 32;
    const int outc = (hh ? 1536 : 0) + n0;

    // ---- PDL prologue: everything independent of the predecessor ----
    // stage the full 32x512 weight slice (each row = 64 uint4)
#pragma unroll
    for (int i = 0; i < 8; ++i) {
        int idx = tid + i * 256;         // 2048 uint4
        int j = idx >> 6, q = idx & 63;
        *(uint4*)&Ball[j][q * 8] =
            *(const uint4*)&W[(size_t)(n0 + j) * ldw + koff + q * 8];
    }
    // stage accumulators (giEmb for gi half, zero for gh half)
    wmma::fragment<wmma::accumulator, 16, 16, 16, float> c[2];
    if (hh) {
        wmma::fill_fragment(c[0], 0.f);
        wmma::fill_fragment(c[1], 0.f);
    } else {
        const float* gi = g_giEmb + ((size_t)step * 128 + wid * 16) * 1536 + n0;
        wmma::load_matrix_sync(c[0], gi, 1536, wmma::mem_row_major);
        wmma::load_matrix_sync(c[1], gi + 16, 1536, wmma::mem_row_major);
    }

    // ---- wait for predecessor (fused step-1 / attn0) ----
    gdc_wait();

    // stage full A (128x512 bf16 = 8192 uint4, 64 uint4 per row)
#pragma unroll
    for (int i = 0; i < 32; ++i) {
        int idx = tid + i * 256;
        int m = idx >> 6, q = idx & 63;
        *(uint4*)&As[m][q * 8] = *(const uint4*)&A[(size_t)m * 512 + q * 8];
    }
    __syncthreads();

#pragma unroll 8
    for (int kk = 0; kk < 512; kk += 16) {
        wmma::fragment<wmma::matrix_a, 16, 16, 16, __nv_bfloat16, wmma::row_major> a;
        wmma::load_matrix_sync(a, &As[wid * 16][kk], 512);
#pragma unroll
        for (int j = 0; j < 2; ++j) {
            wmma::fragment<wmma::matrix_b, 16, 16, 16, __nv_bfloat16, wmma::col_major> bf;
            wmma::load_matrix_sync(bf, &Ball[j * 16][kk], 512);
            wmma::mma_sync(c[j], a, bf, c[j]);
        }
    }
#pragma unroll
    for (int j = 0; j < 2; ++j)
        wmma::store_matrix_sync(&g_gates[(size_t)(wid * 16) * 3072 + outc + j * 16],
                                c[j], 3072, wmma::mem_row_major);
    gdc_launch();
}

// ------ fused: GRU pointwise + h store + sEmb + attention (PDL) ------------------
// grid 128, 1024 threads
__global__ void fused_kernel(const float* __restrict__ b_ih,
                             const float* __restrict__ b_hh,
                             const float* __restrict__ wo,
                             const float* __restrict__ bo,
                             const float* __restrict__ bs,
                             int step) {
    const int b = blockIdx.x;
    const int tid = threadIdx.x;
    __shared__ float hs[512], sE[512], wos[512], ew[256];
    __shared__ float red[16], redv[2];
    __shared__ float sPart[8 * 512];

    // PDL prologue: independent loads
    float bi_r = 0.f, bi_z = 0.f, bi_n = 0.f, bh_r = 0.f, bh_z = 0.f, bh_n = 0.f;
    float h_prev = 0.f;
    if (tid < 512) {
        wos[tid] = wo[tid];
        bi_r = b_ih[tid];
        bi_z = b_ih[tid + 512];
        bi_n = b_ih[tid + 1024];
        bh_r = b_hh[tid];
        bh_z = b_hh[tid + 512];
        bh_n = b_hh[tid + 1024];
        if (step > 0)
            h_prev = g_hHist[((size_t)(step - 1) * BB + b) * 512 + tid];
    }

    gdc_wait();  // wait for gates(step)

    // ---- GRU pointwise update ----
    if (tid < 512) {
        const float* g = g_gates + b * 3072;
        float gir = g[tid] + bi_r;
        float giz = g[tid + 512] + bi_z;
        float gin = g[tid + 1024] + bi_n;
        float ghr = g[tid + 1536] + bh_r;
        float ghz = g[tid + 2048] + bh_z;
        float ghn = g[tid + 2560] + bh_n;
        float r = 1.f / (1.f + __expf(-(gir + ghr)));
        float z = 1.f / (1.f + __expf(-(giz + ghz)));
        float n = fast_tanh(gin + r * ghn);
        float hv = (1.f - z) * n + z * h_prev;
        g_hHist[((size_t)step * BB + b) * 512 + tid] = hv;
        g_h16[b * 512 + tid] = __float2bfloat16(hv);
        hs[tid] = hv;
    }
    __syncthreads();

    if (step == ML - 1) {
        gdc_launch();
        return;
    }

    // ---- sEmb = h @ Ws + bs (8-way k-split over 1024 threads) ----
    {
        const int ks = tid >> 7;
        const int n0 = (tid & 127) * 4;
        float acc0 = 0.f, acc1 = 0.f, acc2 = 0.f, acc3 = 0.f;
#pragma unroll 4
        for (int kk = 0; kk < 64; ++kk) {
            int k = ks * 64 + kk;
            float hk = hs[k];
            union { uint2 u; __nv_bfloat162 h2[2]; } U;
            U.u = *(const uint2*)&g_Ws16[k * 512 + n0];
            float2 w0 = __bfloat1622float2(U.h2[0]);
            float2 w1 = __bfloat1622float2(U.h2[1]);
            acc0 = fmaf(hk, w0.x, acc0);
            acc1 = fmaf(hk, w0.y, acc1);
            acc2 = fmaf(hk, w1.x, acc2);
            acc3 = fmaf(hk, w1.y, acc3);
        }
        sPart[ks * 512 + n0] = acc0;
        sPart[ks * 512 + n0 + 1] = acc1;
        sPart[ks * 512 + n0 + 2] = acc2;
        sPart[ks * 512 + n0 + 3] = acc3;
    }
    __syncthreads();
    if (tid < 512) {
        float s = bs[tid];
#pragma unroll
        for (int i = 0; i < 8; ++i) s += sPart[i * 512 + tid];
        sE[tid] = s;
    }
    __syncthreads();

    attn_body(b, tid, sE, wos, ew, red, redv, sPart, bo);
    gdc_launch();
}

// ------ final: logits + log-softmax for all 3328 rows (PDL) ----------------------
__global__ void out_final_kernel(const float* __restrict__ bout,
                                 float* __restrict__ out) {
    const int m0 = blockIdx.x * 8;
    const int tid = threadIdx.x;
    __shared__ float hs8[8][512];
    __shared__ float lg[8][96];

    gdc_wait();

    for (int i = tid; i < 8 * 512; i += 512)
        hs8[i >> 9][i & 511] = g_hHist[(size_t)m0 * 512 + i];
    __syncthreads();

    for (int i = tid; i < 8 * CC; i += 512) {
        int r = i / CC, c = i % CC;
        const float4* wp = (const float4*)(g_WoutT + c * 512);
        const float4* hp = (const float4*)hs8[r];
        float acc = 0.f;
#pragma unroll 16
        for (int k = 0; k < 128; ++k) {
            float4 h4 = hp[k], w4 = wp[k];
            acc = fmaf(h4.x, w4.x, acc);
            acc = fmaf(h4.y, w4.y, acc);
            acc = fmaf(h4.z, w4.z, acc);
            acc = fmaf(h4.w, w4.w, acc);
        }
        lg[r][c] = acc + bout[c];
    }
    __syncthreads();

    const int warp = tid >> 5, lane = tid & 31;
    if (warp < 8) {
        float v0 = (lane < CC) ? lg[warp][lane] : -1e30f;
        float v1 = (lane + 32 < CC) ? lg[warp][lane + 32] : -1e30f;
        float v2 = (lane + 64 < CC) ? lg[warp][lane + 64] : -1e30f;
        float m = fmaxf(v0, fmaxf(v1, v2));
#pragma unroll
        for (int off = 16; off > 0; off >>= 1)
            m = fmaxf(m, __shfl_xor_sync(0xffffffffu, m, off));
        float s = ((lane < CC) ? __expf(v0 - m) : 0.f) +
                  ((lane + 32 < CC) ? __expf(v1 - m) : 0.f) +
                  ((lane + 64 < CC) ? __expf(v2 - m) : 0.f);
#pragma unroll
        for (int off = 16; off > 0; off >>= 1)
            s += __shfl_xor_sync(0xffffffffu, s, off);
        float lse = m + logf(s);
        float* o = out + (size_t)(m0 + warp) * CC;
        if (lane < CC) o[lane] = v0 - lse;
        if (lane + 32 < CC) o[lane + 32] = v1 - lse;
        if (lane + 64 < CC) o[lane + 64] = v2 - lse;
    }
}

// ---------------- PDL launch helper ----------------------------------------------
template <class F, class... A>
static inline void pdl_launch(F f, dim3 g, dim3 b, size_t smem, A... args) {
    cudaLaunchConfig_t cfg = {};
    cfg.gridDim = g;
    cfg.blockDim = b;
    cfg.dynamicSmemBytes = smem;
    cfg.stream = 0;
    cudaLaunchAttribute at[1];
    at[0].id = cudaLaunchAttributeProgrammaticStreamSerialization;
    at[0].val.programmaticStreamSerializationAllowed = 1;
    cfg.attrs = at;
    cfg.numAttrs = 1;
    cudaLaunchKernelEx(&cfg, f, args...);
}

// --------------------------------- launcher --------------------------------------
extern "C" void kernel_launch(void* const* d_in, const int* in_sizes, int n_in,
                              void* d_out, int out_size) {
    (void)in_sizes; (void)n_in; (void)out_size;
    const float* x       = (const float*)d_in[0];
    const int*   targets = (const int*)  d_in[1];
    const float* emb     = (const float*)d_in[2];
    const float* Wi      = (const float*)d_in[3];
    const float* bi      = (const float*)d_in[4];
    const float* Ws      = (const float*)d_in[5];
    const float* bs      = (const float*)d_in[6];
    const float* wo      = (const float*)d_in[7];
    const float* bo      = (const float*)d_in[8];
    const float* W_ih    = (const float*)d_in[9];
    const float* W_hh    = (const float*)d_in[10];
    const float* b_ih    = (const float*)d_in[11];
    const float* b_hh    = (const float*)d_in[12];
    const float* Wout    = (const float*)d_in[13];
    const float* bout    = (const float*)d_in[14];
    float* out = (float*)d_out;

    static bool attr_set = false;
    if (!attr_set) {
        cudaFuncSetAttribute(xemb_wmma_kernel,
                             cudaFuncAttributeMaxDynamicSharedMemorySize, 81920);
        cudaFuncSetAttribute(gates_kernel,
                             cudaFuncAttributeMaxDynamicSharedMemorySize, 163840);
        attr_set = true;
    }

    // one-time (merged): launch #0
    prep_kernel<<<21023, 256>>>(x, Wi, Ws, W_ih, W_hh, Wout, emb, targets);
    // launch #1
    xemb_wmma_kernel<<<dim3(4, 256), 256, 81920>>>(bi);
    // launch #2
    giemb_wmma_kernel<<<dim3(1536 / 64, ML * BB / 128), 256>>>();
    // launch #3: step 0 attention (h = 0)
    attn0_kernel<<<BB, 1024>>>(wo, bo, bs);

    for (int step = 0; step < ML; ++step) {
        // launch #4, #6, ... (gates) ; #5, #7, ... (fused) — #5 is ncu-captured
        pdl_launch(gates_kernel, dim3(96), dim3(256), (size_t)163840, step);
        pdl_launch(fused_kernel, dim3(BB), dim3(1024), (size_t)0,
                   b_ih, b_hh, wo, bo, bs, step);
    }

    // all outputs at once (off the critical path)
    pdl_launch(out_final_kernel, dim3(ML * BB / 8), dim3(512), (size_t)0,
               bout, out);
}

// round 15
// speedup vs baseline: 1.5350x; 1.3706x over previous
#include <cuda_runtime.h>
#include <cuda_bf16.h>
#include <cuda_fp16.h>
#include <mma.h>
#include <math.h>

using namespace nvcuda;

#define BB 128
#define TT 256
#define LL 512
#define HH 512
#define CC 95
#define ML 26

// ---------------- device scratch (static: no runtime allocation) ----------------
__device__ __align__(16) __nv_bfloat16 g_x16[BB * TT * LL];     // 32 MB
__device__ __align__(16) __half g_xEmb16[BB * TT * HH];         // 32 MB (fp16!)
__device__ __align__(16) __nv_bfloat16 g_Wi16[LL * HH];
__device__ __align__(16) __nv_bfloat16 g_Ws16[HH * HH];
__device__ __align__(16) __nv_bfloat16 g_Wih16[1536 * 1024];
__device__ __align__(16) __nv_bfloat16 g_Whh16[1536 * 512];
__device__ __align__(16) __nv_bfloat16 g_embSeq[ML * BB * HH];
__device__ __align__(16) float g_giEmb[ML * BB * 1536];         // 20 MB
__device__ __align__(16) float g_WoutT[CC * HH];
__device__ __align__(16) float g_hHist[ML * BB * HH];           // 6.8 MB
__device__ __align__(16) __nv_bfloat16 g_h16[BB * HH];
__device__ __align__(16) __nv_bfloat16 g_ctx16[BB * HH];
__device__ __align__(16) float g_gates[BB * 3072];

// ---------------- PDL intrinsics -------------------------------------------------
__device__ __forceinline__ void gdc_wait() {
    asm volatile("griddepcontrol.wait;" ::: "memory");
}
__device__ __forceinline__ void gdc_launch() {
    asm volatile("griddepcontrol.launch_dependents;" ::: "memory");
}

// ---------------- fast math ------------------------------------------------------
__device__ __forceinline__ __half2 tanh2(__half2 x) {
    __half2 y;
    asm("tanh.approx.f16x2 %0, %1;"
        : "=r"(*(unsigned*)&y) : "r"(*(unsigned*)&x));
    return y;
}

__device__ __forceinline__ float fast_rcp_pos(float q) {
    float r = __uint_as_float(0x7EF127EAu - __float_as_uint(q));
    r = r * (2.0f - q * r);
    r = r * (2.0f - q * r);
    return r;
}

__device__ __forceinline__ float fast_tanh(float x) {  // accurate FMA-only (GRU n)
    float cx = fminf(fmaxf(x, -7.90531110763549805f), 7.90531110763549805f);
    float x2 = cx * cx;
    float p = fmaf(x2, -8.60467152213735e-11f, 5.12229709037114e-08f);
    p = fmaf(p, x2, 1.48572235717979e-05f);
    p = fmaf(p, x2, 6.37261928875436e-04f);
    p = fmaf(p, x2, 4.89352455891786e-03f);
    p = cx * p;
    float q = fmaf(x2, 1.19825839466702e-06f, 1.18534705686654e-04f);
    q = fmaf(q, x2, 2.26843463243900e-03f);
    q = fmaf(q, x2, 4.89352518554385e-03f);
    return p * fast_rcp_pos(q);
}

// ---------------- ONE merged prep kernel (all one-time conversions) --------------
__device__ __forceinline__ void cvt4(const float* __restrict__ src,
                                     __nv_bfloat16* __restrict__ dst, int i) {
    float4 v = *(const float4*)(src + i);
    __nv_bfloat162* o = (__nv_bfloat162*)(dst + i);
    o[0] = __floats2bfloat162_rn(v.x, v.y);
    o[1] = __floats2bfloat162_rn(v.z, v.w);
}

__global__ void prep_kernel(const float* __restrict__ x,
                            const float* __restrict__ Wi,
                            const float* __restrict__ Ws,
                            const float* __restrict__ W_ih,
                            const float* __restrict__ W_hh,
                            const float* __restrict__ Wout,
                            const float* __restrict__ emb,
                            const int* __restrict__ targets) {
    const int blk = blockIdx.x;
    const int tid = threadIdx.x;
    if (blk < 16384) {                       // x -> bf16
        cvt4(x, g_x16, blk * 1024 + tid * 4);
    } else if (blk < 16640) {                // Wi
        cvt4(Wi, g_Wi16, (blk - 16384) * 1024 + tid * 4);
    } else if (blk < 16896) {                // Ws
        cvt4(Ws, g_Ws16, (blk - 16640) * 1024 + tid * 4);
    } else if (blk < 18432) {                // W_ih
        cvt4(W_ih, g_Wih16, (blk - 16896) * 1024 + tid * 4);
    } else if (blk < 19200) {                // W_hh
        cvt4(W_hh, g_Whh16, (blk - 18432) * 1024 + tid * 4);
    } else if (blk < 19295) {                // Wout transpose
        int c = blk - 19200;
        g_WoutT[c * HH + tid] = Wout[tid * CC + c];
        g_WoutT[c * HH + tid + 256] = Wout[(tid + 256) * CC + c];
    } else if (blk < 20959) {                // teacher-forced emb gather (bf16)
        int e = (blk - 19295) * 1024 + tid * 4;
        int m = e >> 9, k = e & 511;
        int step = m >> 7, b = m & 127;
        int y = (step == 0) ? CC : targets[b * ML + step - 1];
        float4 v = *(const float4*)(emb + y * HH + k);
        __nv_bfloat162* o = (__nv_bfloat162*)(g_embSeq + (size_t)m * HH + k);
        o[0] = __floats2bfloat162_rn(v.x, v.y);
        o[1] = __floats2bfloat162_rn(v.z, v.w);
    } else {                                 // h16 = 0
        int i = (blk - 20959) * 1024 + tid * 4;
        __nv_bfloat162 z = __floats2bfloat162_rn(0.f, 0.f);
        __nv_bfloat162* o = (__nv_bfloat162*)(g_h16 + i);
        o[0] = z;
        o[1] = z;
    }
}

// ---------------- one-time: xEmb = x @ Wi + bi (bf16 wmma -> fp16 out) -----------
__global__ void xemb_wmma_kernel(const float* __restrict__ bias) {
    extern __shared__ char dyn[];
    __nv_bfloat16 (*As)[32] = (__nv_bfloat16(*)[32])dyn;
    __nv_bfloat16 (*Bs)[128] = (__nv_bfloat16(*)[128])(dyn + 8192);
    float (*Co)[128] = (float(*)[128])(dyn + 16384);
    const int tid = threadIdx.x;
    const int wid = tid >> 5;
    const int m0 = blockIdx.y * 128;
    const int n0 = blockIdx.x * 128;
    const int warpM = wid & 3;
    const int warpN = wid >> 2;

    wmma::fragment<wmma::accumulator, 16, 16, 16, float> c[2][4];
#pragma unroll
    for (int i = 0; i < 2; ++i)
#pragma unroll
        for (int j = 0; j < 4; ++j) wmma::fill_fragment(c[i][j], 0.f);

    for (int k0 = 0; k0 < 512; k0 += 32) {
#pragma unroll
        for (int i = 0; i < 2; ++i) {
            int idx = tid + i * 256;
            int m = idx >> 2, kq = idx & 3;
            *(uint4*)&As[m][kq * 8] =
                *(const uint4*)&g_x16[(size_t)(m0 + m) * 512 + k0 + kq * 8];
        }
#pragma unroll
        for (int i = 0; i < 2; ++i) {
            int idx = tid + i * 256;
            int k = idx >> 4, q = idx & 15;
            *(uint4*)&Bs[k][q * 8] =
                *(const uint4*)&g_Wi16[(size_t)(k0 + k) * 512 + n0 + q * 8];
        }
        __syncthreads();
#pragma unroll
        for (int kk = 0; kk < 32; kk += 16) {
            wmma::fragment<wmma::matrix_a, 16, 16, 16, __nv_bfloat16, wmma::row_major> a[2];
            wmma::fragment<wmma::matrix_b, 16, 16, 16, __nv_bfloat16, wmma::row_major> b[4];
#pragma unroll
            for (int i = 0; i < 2; ++i)
                wmma::load_matrix_sync(a[i], &As[warpM * 32 + i * 16][kk], 32);
#pragma unroll
            for (int j = 0; j < 4; ++j)
                wmma::load_matrix_sync(b[j], &Bs[kk][warpN * 64 + j * 16], 128);
#pragma unroll
            for (int i = 0; i < 2; ++i)
#pragma unroll
                for (int j = 0; j < 4; ++j)
                    wmma::mma_sync(c[i][j], a[i], b[j], c[i][j]);
        }
        __syncthreads();
    }
#pragma unroll
    for (int i = 0; i < 2; ++i)
#pragma unroll
        for (int j = 0; j < 4; ++j)
            wmma::store_matrix_sync(&Co[warpM * 32 + i * 16][warpN * 64 + j * 16],
                                    c[i][j], 128, wmma::mem_row_major);
    __syncthreads();
#pragma unroll
    for (int it = 0; it < 64; ++it) {
        int idx = it * 256 + tid;
        int m = idx >> 7, cc = idx & 127;
        g_xEmb16[(size_t)(m0 + m) * 512 + n0 + cc] =
            __float2half(Co[m][cc] + bias[n0 + cc]);
    }
}

// ------ one-time: giEmb = embSeq @ W_ih[:, :512]^T  [3328,1536] fp32 -------------
__global__ void giemb_wmma_kernel() {
    __shared__ __nv_bfloat16 As[128][32];
    __shared__ __nv_bfloat16 Bs[64][32];
    const int tid = threadIdx.x;
    const int wid = tid >> 5;
    const int m0 = blockIdx.y * 128;
    const int n0 = blockIdx.x * 64;

    wmma::fragment<wmma::accumulator, 16, 16, 16, float> c[4];
#pragma unroll
    for (int j = 0; j < 4; ++j) wmma::fill_fragment(c[j], 0.f);

    for (int k0 = 0; k0 < 512; k0 += 32) {
#pragma unroll
        for (int i = 0; i < 2; ++i) {
            int idx = tid + i * 256;
            int m = idx >> 2, kq = idx & 3;
            *(uint4*)&As[m][kq * 8] =
                *(const uint4*)&g_embSeq[(size_t)(m0 + m) * 512 + k0 + kq * 8];
        }
        {
            int j = tid >> 2, kq = tid & 3;
            *(uint4*)&Bs[j][kq * 8] =
                *(const uint4*)&g_Wih16[(size_t)(n0 + j) * 1024 + k0 + kq * 8];
        }
        __syncthreads();
#pragma unroll
        for (int kk = 0; kk < 32; kk += 16) {
            wmma::fragment<wmma::matrix_a, 16, 16, 16, __nv_bfloat16, wmma::row_major> a;
            wmma::load_matrix_sync(a, &As[wid * 16][kk], 32);
#pragma unroll
            for (int j = 0; j < 4; ++j) {
                wmma::fragment<wmma::matrix_b, 16, 16, 16, __nv_bfloat16, wmma::col_major> bf;
                wmma::load_matrix_sync(bf, &Bs[j * 16][kk], 32);
                wmma::mma_sync(c[j], a, bf, c[j]);
            }
        }
        __syncthreads();
    }
#pragma unroll
    for (int j = 0; j < 4; ++j)
        wmma::store_matrix_sync(&g_giEmb[(size_t)(m0 + wid * 16) * 1536 + n0 + j * 16],
                                c[j], 1536, wmma::mem_row_major);
}

// ---------------- attention body: register-resident e-score + vector ctx ---------
// needs: sE[512], wos[512] in shared (16B aligned); sPart = 16*512 floats
__device__ __forceinline__ void attn_body(int b, int tid,
                                          const float* sE, const float* wos,
                                          float* ew, float* red, float* redv,
                                          float* sPart, const float* bo) {
    const int lane = tid & 31, warp = tid >> 5;

    // ---- e-scores: warp handles 8 t; lane owns cols [lane*8,+8) and [256+lane*8,+8)
    {
        float wo_r[16];
        __half2 sE2[8];
        {
            float4 w0 = *(const float4*)&wos[lane * 8];
            float4 w1 = *(const float4*)&wos[lane * 8 + 4];
            float4 w2 = *(const float4*)&wos[256 + lane * 8];
            float4 w3 = *(const float4*)&wos[256 + lane * 8 + 4];
            wo_r[0] = w0.x; wo_r[1] = w0.y; wo_r[2] = w0.z; wo_r[3] = w0.w;
            wo_r[4] = w1.x; wo_r[5] = w1.y; wo_r[6] = w1.z; wo_r[7] = w1.w;
            wo_r[8] = w2.x; wo_r[9] = w2.y; wo_r[10] = w2.z; wo_r[11] = w2.w;
            wo_r[12] = w3.x; wo_r[13] = w3.y; wo_r[14] = w3.z; wo_r[15] = w3.w;
            float4 s0 = *(const float4*)&sE[lane * 8];
            float4 s1 = *(const float4*)&sE[lane * 8 + 4];
            float4 s2 = *(const float4*)&sE[256 + lane * 8];
            float4 s3 = *(const float4*)&sE[256 + lane * 8 + 4];
            sE2[0] = __floats2half2_rn(s0.x, s0.y);
            sE2[1] = __floats2half2_rn(s0.z, s0.w);
            sE2[2] = __floats2half2_rn(s1.x, s1.y);
            sE2[3] = __floats2half2_rn(s1.z, s1.w);
            sE2[4] = __floats2half2_rn(s2.x, s2.y);
            sE2[5] = __floats2half2_rn(s2.z, s2.w);
            sE2[6] = __floats2half2_rn(s3.x, s3.y);
            sE2[7] = __floats2half2_rn(s3.z, s3.w);
        }
        const float bov = bo[0];
#pragma unroll
        for (int r = 0; r < 8; ++r) {
            int t = warp * 8 + r;
            const uint4* row = (const uint4*)(g_xEmb16 + ((size_t)(b * 256 + t)) * 512);
            uint4 u0 = row[lane];        // cols [lane*8, +8)
            uint4 u1 = row[lane + 32];   // cols [256+lane*8, +8)
            const __half2* x0 = (const __half2*)&u0;
            const __half2* x1 = (const __half2*)&u1;
            float acc = 0.f;
#pragma unroll
            for (int j = 0; j < 4; ++j) {
                float2 t0 = __half22float2(tanh2(__hadd2(x0[j], sE2[j])));
                acc = fmaf(wo_r[2 * j], t0.x, acc);
                acc = fmaf(wo_r[2 * j + 1], t0.y, acc);
                float2 t1 = __half22float2(tanh2(__hadd2(x1[j], sE2[4 + j])));
                acc = fmaf(wo_r[8 + 2 * j], t1.x, acc);
                acc = fmaf(wo_r[8 + 2 * j + 1], t1.y, acc);
            }
#pragma unroll
            for (int off = 16; off > 0; off >>= 1)
                acc += __shfl_xor_sync(0xffffffffu, acc, off);
            if (lane == 0) ew[t] = acc + bov;
        }
    }
    __syncthreads();

    // ---- softmax over ew[256] ----
    if (tid < 256) {
        float v = ew[tid];
        float m = v;
#pragma unroll
        for (int off = 16; off > 0; off >>= 1)
            m = fmaxf(m, __shfl_xor_sync(0xffffffffu, m, off));
        if ((tid & 31) == 0) red[tid >> 5] = m;
    }
    __syncthreads();
    if (tid == 0) {
        float m = red[0];
#pragma unroll
        for (int w = 1; w < 8; ++w) m = fmaxf(m, red[w]);
        redv[0] = m;
    }
    __syncthreads();
    if (tid < 256) {
        float p = __expf(ew[tid] - redv[0]);
        ew[tid] = p;
        float s = p;
#pragma unroll
        for (int off = 16; off > 0; off >>= 1)
            s += __shfl_xor_sync(0xffffffffu, s, off);
        if ((tid & 31) == 0) red[8 + (tid >> 5)] = s;
    }
    __syncthreads();
    if (tid == 0) {
        float s = 0.f;
#pragma unroll
        for (int w = 0; w < 8; ++w) s += red[8 + w];
        redv[1] = 1.0f / s;
    }
    __syncthreads();
    if (tid < 256) ew[tid] *= redv[1];
    __syncthreads();

    // ---- ctx = aw @ x[b]: 16-way t-split, 64 col-groups of 8 ----
    {
        const int tq = tid >> 6;           // 0..15, t in [tq*16, +16)
        const int g = tid & 63;            // cols [g*8, +8)
        float a0 = 0.f, a1 = 0.f, a2 = 0.f, a3 = 0.f;
        float a4 = 0.f, a5 = 0.f, a6 = 0.f, a7 = 0.f;
        const uint4* xb = (const uint4*)(g_x16 + ((size_t)b * 256 + tq * 16) * 512) + g;
#pragma unroll
        for (int tt = 0; tt < 16; ++tt) {
            float aw = ew[tq * 16 + tt];
            uint4 u = xb[(size_t)tt * 64];
            const __nv_bfloat162* v2 = (const __nv_bfloat162*)&u;
            float2 v0 = __bfloat1622float2(v2[0]);
            float2 v1 = __bfloat1622float2(v2[1]);
            float2 v22 = __bfloat1622float2(v2[2]);
            float2 v3 = __bfloat1622float2(v2[3]);
            a0 = fmaf(aw, v0.x, a0);
            a1 = fmaf(aw, v0.y, a1);
            a2 = fmaf(aw, v1.x, a2);
            a3 = fmaf(aw, v1.y, a3);
            a4 = fmaf(aw, v22.x, a4);
            a5 = fmaf(aw, v22.y, a5);
            a6 = fmaf(aw, v3.x, a6);
            a7 = fmaf(aw, v3.y, a7);
        }
        float* p = &sPart[tq * 512 + g * 8];
        *(float4*)p = make_float4(a0, a1, a2, a3);
        *(float4*)(p + 4) = make_float4(a4, a5, a6, a7);
    }
    __syncthreads();
    if (tid < 512) {
        float c = 0.f;
#pragma unroll
        for (int i = 0; i < 16; ++i) c += sPart[i * 512 + tid];
        g_ctx16[b * 512 + tid] = __float2bfloat16(c);
    }
}

// ---------------- step 0 attention (h = 0 -> sEmb = bs) --------------------------
__global__ __launch_bounds__(1024, 1)
void attn0_kernel(const float* __restrict__ wo,
                  const float* __restrict__ bo,
                  const float* __restrict__ bs) {
    const int b = blockIdx.x;
    const int tid = threadIdx.x;
    __shared__ __align__(16) float sE[512];
    __shared__ __align__(16) float wos[512];
    __shared__ __align__(16) float ew[256];
    __shared__ float red[16], redv[2];
    __shared__ __align__(16) float sPart[16 * 512];
    if (tid < 512) {
        sE[tid] = bs[tid];
        wos[tid] = wo[tid];
    }
    __syncthreads();
    attn_body(b, tid, sE, wos, ew, red, redv, sPart, bo);
}

// ---------- per-step gates GEMM: PDL + full-tile smem staging --------------------
// grid 96 (48 gi + 48 gh), 256 threads. dyn smem: A 128x512 (128KB) + B 32x512 (32KB)
__global__ void gates_kernel(int step) {
    extern __shared__ char dyn[];
    __nv_bfloat16 (*As)[512] = (__nv_bfloat16(*)[512])dyn;
    __nv_bfloat16 (*Ball)[512] = (__nv_bfloat16(*)[512])(dyn + 131072);
    const int tid = threadIdx.x;
    const int wid = tid >> 5;
    const bool hh = blockIdx.x >= 48;
    const __nv_bfloat16* A = hh ? g_h16 : g_ctx16;
    const __nv_bfloat16* W = hh ? g_Whh16 : g_Wih16;
    const int ldw = hh ? 512 : 1024;
    const int koff = hh ? 0 : 512;
    const int n0 = (hh ? blockIdx.x - 48 : blockIdx.x) * 32;
    const int outc = (hh ? 1536 : 0) + n0;

    // ---- PDL prologue: everything independent of the predecessor ----
#pragma unroll
    for (int i = 0; i < 8; ++i) {
        int idx = tid + i * 256;         // 2048 uint4, 64 per row
        int j = idx >> 6, q = idx & 63;
        *(uint4*)&Ball[j][q * 8] =
            *(const uint4*)&W[(size_t)(n0 + j) * ldw + koff + q * 8];
    }
    wmma::fragment<wmma::accumulator, 16, 16, 16, float> c[2];
    if (hh) {
        wmma::fill_fragment(c[0], 0.f);
        wmma::fill_fragment(c[1], 0.f);
    } else {
        const float* gi = g_giEmb + ((size_t)step * 128 + wid * 16) * 1536 + n0;
        wmma::load_matrix_sync(c[0], gi, 1536, wmma::mem_row_major);
        wmma::load_matrix_sync(c[1], gi + 16, 1536, wmma::mem_row_major);
    }

    gdc_wait();

    // stage full A (128x512 bf16 = 8192 uint4, 64 per row)
#pragma unroll
    for (int i = 0; i < 32; ++i) {
        int idx = tid + i * 256;
        int m = idx >> 6, q = idx & 63;
        *(uint4*)&As[m][q * 8] = *(const uint4*)&A[(size_t)m * 512 + q * 8];
    }
    __syncthreads();

#pragma unroll 8
    for (int kk = 0; kk < 512; kk += 16) {
        wmma::fragment<wmma::matrix_a, 16, 16, 16, __nv_bfloat16, wmma::row_major> a;
        wmma::load_matrix_sync(a, &As[wid * 16][kk], 512);
#pragma unroll
        for (int j = 0; j < 2; ++j) {
            wmma::fragment<wmma::matrix_b, 16, 16, 16, __nv_bfloat16, wmma::col_major> bf;
            wmma::load_matrix_sync(bf, &Ball[j * 16][kk], 512);
            wmma::mma_sync(c[j], a, bf, c[j]);
        }
    }
#pragma unroll
    for (int j = 0; j < 2; ++j)
        wmma::store_matrix_sync(&g_gates[(size_t)(wid * 16) * 3072 + outc + j * 16],
                                c[j], 3072, wmma::mem_row_major);
    gdc_launch();
}

// ------ fused: GRU pointwise + h store + sEmb + attention (PDL) ------------------
// grid 128, 1024 threads
__global__ __launch_bounds__(1024, 1)
void fused_kernel(const float* __restrict__ b_ih,
                  const float* __restrict__ b_hh,
                  const float* __restrict__ wo,
                  const float* __restrict__ bo,
                  const float* __restrict__ bs,
                  int step) {
    const int b = blockIdx.x;
    const int tid = threadIdx.x;
    __shared__ __align__(16) float hs[512];
    __shared__ __align__(16) float sE[512];
    __shared__ __align__(16) float wos[512];
    __shared__ __align__(16) float ew[256];
    __shared__ float red[16], redv[2];
    __shared__ __align__(16) float sPart[16 * 512];

    // PDL prologue: independent loads
    float bi_r = 0.f, bi_z = 0.f, bi_n = 0.f, bh_r = 0.f, bh_z = 0.f, bh_n = 0.f;
    float h_prev = 0.f;
    if (tid < 512) {
        wos[tid] = wo[tid];
        bi_r = b_ih[tid];
        bi_z = b_ih[tid + 512];
        bi_n = b_ih[tid + 1024];
        bh_r = b_hh[tid];
        bh_z = b_hh[tid + 512];
        bh_n = b_hh[tid + 1024];
        if (step > 0)
            h_prev = g_hHist[((size_t)(step - 1) * BB + b) * 512 + tid];
    }

    gdc_wait();  // wait for gates(step)

    // ---- GRU pointwise update ----
    if (tid < 512) {
        const float* g = g_gates + b * 3072;
        float gir = g[tid] + bi_r;
        float giz = g[tid + 512] + bi_z;
        float gin = g[tid + 1024] + bi_n;
        float ghr = g[tid + 1536] + bh_r;
        float ghz = g[tid + 2048] + bh_z;
        float ghn = g[tid + 2560] + bh_n;
        float r = 1.f / (1.f + __expf(-(gir + ghr)));
        float z = 1.f / (1.f + __expf(-(giz + ghz)));
        float n = fast_tanh(gin + r * ghn);
        float hv = (1.f - z) * n + z * h_prev;
        g_hHist[((size_t)step * BB + b) * 512 + tid] = hv;
        g_h16[b * 512 + tid] = __float2bfloat16(hv);
        hs[tid] = hv;
    }
    __syncthreads();

    if (step == ML - 1) {
        gdc_launch();
        return;
    }

    // ---- sEmb = h @ Ws + bs (16-way k-split, uint4 weight loads) ----
    {
        const int ks = tid >> 6;          // 0..15, k in [ks*32, +32)
        const int g = tid & 63;           // cols [g*8, +8)
        float a0 = 0.f, a1 = 0.f, a2 = 0.f, a3 = 0.f;
        float a4 = 0.f, a5 = 0.f, a6 = 0.f, a7 = 0.f;
        const uint4* wrow = (const uint4*)(g_Ws16 + (size_t)(ks * 32) * 512) + g;
#pragma unroll 4
        for (int kk = 0; kk < 32; ++kk) {
            float hk = hs[ks * 32 + kk];
            uint4 u = wrow[(size_t)kk * 64];
            const __nv_bfloat162* w2 = (const __nv_bfloat162*)&u;
            float2 w0 = __bfloat1622float2(w2[0]);
            float2 w1 = __bfloat1622float2(w2[1]);
            float2 wv2 = __bfloat1622float2(w2[2]);
            float2 w3 = __bfloat1622float2(w2[3]);
            a0 = fmaf(hk, w0.x, a0);
            a1 = fmaf(hk, w0.y, a1);
            a2 = fmaf(hk, w1.x, a2);
            a3 = fmaf(hk, w1.y, a3);
            a4 = fmaf(hk, wv2.x, a4);
            a5 = fmaf(hk, wv2.y, a5);
            a6 = fmaf(hk, w3.x, a6);
            a7 = fmaf(hk, w3.y, a7);
        }
        float* p = &sPart[ks * 512 + g * 8];
        *(float4*)p = make_float4(a0, a1, a2, a3);
        *(float4*)(p + 4) = make_float4(a4, a5, a6, a7);
    }
    __syncthreads();
    if (tid < 512) {
        float s = bs[tid];
#pragma unroll
        for (int i = 0; i < 16; ++i) s += sPart[i * 512 + tid];
        sE[tid] = s;
    }
    __syncthreads();

    attn_body(b, tid, sE, wos, ew, red, redv, sPart, bo);
    gdc_launch();
}

// ------ final: logits + log-softmax for all 3328 rows (PDL) ----------------------
__global__ void out_final_kernel(const float* __restrict__ bout,
                                 float* __restrict__ out) {
    const int m0 = blockIdx.x * 8;
    const int tid = threadIdx.x;
    __shared__ float hs8[8][512];
    __shared__ float lg[8][96];

    gdc_wait();

    for (int i = tid; i < 8 * 512; i += 512)
        hs8[i >> 9][i & 511] = g_hHist[(size_t)m0 * 512 + i];
    __syncthreads();

    for (int i = tid; i < 8 * CC; i += 512) {
        int r = i / CC, c = i % CC;
        const float4* wp = (const float4*)(g_WoutT + c * 512);
        const float4* hp = (const float4*)hs8[r];
        float acc = 0.f;
#pragma unroll 16
        for (int k = 0; k < 128; ++k) {
            float4 h4 = hp[k], w4 = wp[k];
            acc = fmaf(h4.x, w4.x, acc);
            acc = fmaf(h4.y, w4.y, acc);
            acc = fmaf(h4.z, w4.z, acc);
            acc = fmaf(h4.w, w4.w, acc);
        }
        lg[r][c] = acc + bout[c];
    }
    __syncthreads();

    const int warp = tid >> 5, lane = tid & 31;
    if (warp < 8) {
        float v0 = (lane < CC) ? lg[warp][lane] : -1e30f;
        float v1 = (lane + 32 < CC) ? lg[warp][lane + 32] : -1e30f;
        float v2 = (lane + 64 < CC) ? lg[warp][lane + 64] : -1e30f;
        float m = fmaxf(v0, fmaxf(v1, v2));
#pragma unroll
        for (int off = 16; off > 0; off >>= 1)
            m = fmaxf(m, __shfl_xor_sync(0xffffffffu, m, off));
        float s = ((lane < CC) ? __expf(v0 - m) : 0.f) +
                  ((lane + 32 < CC) ? __expf(v1 - m) : 0.f) +
                  ((lane + 64 < CC) ? __expf(v2 - m) : 0.f);
#pragma unroll
        for (int off = 16; off > 0; off >>= 1)
            s += __shfl_xor_sync(0xffffffffu, s, off);
        float lse = m + logf(s);
        float* o = out + (size_t)(m0 + warp) * CC;
        if (lane < CC) o[lane] = v0 - lse;
        if (lane + 32 < CC) o[lane + 32] = v1 - lse;
        if (lane + 64 < CC) o[lane + 64] = v2 - lse;
    }
}

// ---------------- PDL launch helper ----------------------------------------------
template <class F, class... A>
static inline void pdl_launch(F f, dim3 g, dim3 b, size_t smem, A... args) {
    cudaLaunchConfig_t cfg = {};
    cfg.gridDim = g;
    cfg.blockDim = b;
    cfg.dynamicSmemBytes = smem;
    cfg.stream = 0;
    cudaLaunchAttribute at[1];
    at[0].id = cudaLaunchAttributeProgrammaticStreamSerialization;
    at[0].val.programmaticStreamSerializationAllowed = 1;
    cfg.attrs = at;
    cfg.numAttrs = 1;
    cudaLaunchKernelEx(&cfg, f, args...);
}

// --------------------------------- launcher --------------------------------------
extern "C" void kernel_launch(void* const* d_in, const int* in_sizes, int n_in,
                              void* d_out, int out_size) {
    (void)in_sizes; (void)n_in; (void)out_size;
    const float* x       = (const float*)d_in[0];
    const int*   targets = (const int*)  d_in[1];
    const float* emb     = (const float*)d_in[2];
    const float* Wi      = (const float*)d_in[3];
    const float* bi      = (const float*)d_in[4];
    const float* Ws      = (const float*)d_in[5];
    const float* bs      = (const float*)d_in[6];
    const float* wo      = (const float*)d_in[7];
    const float* bo      = (const float*)d_in[8];
    const float* W_ih    = (const float*)d_in[9];
    const float* W_hh    = (const float*)d_in[10];
    const float* b_ih    = (const float*)d_in[11];
    const float* b_hh    = (const float*)d_in[12];
    const float* Wout    = (const float*)d_in[13];
    const float* bout    = (const float*)d_in[14];
    float* out = (float*)d_out;

    static bool attr_set = false;
    if (!attr_set) {
        cudaFuncSetAttribute(xemb_wmma_kernel,
                             cudaFuncAttributeMaxDynamicSharedMemorySize, 81920);
        cudaFuncSetAttribute(gates_kernel,
                             cudaFuncAttributeMaxDynamicSharedMemorySize, 163840);
        attr_set = true;
    }

    // one-time (merged): launch #0
    prep_kernel<<<21023, 256>>>(x, Wi, Ws, W_ih, W_hh, Wout, emb, targets);
    // launch #1
    xemb_wmma_kernel<<<dim3(4, 256), 256, 81920>>>(bi);
    // launch #2
    giemb_wmma_kernel<<<dim3(1536 / 64, ML * BB / 128), 256>>>();
    // launch #3: step 0 attention (h = 0)
    attn0_kernel<<<BB, 1024>>>(wo, bo, bs);

    for (int step = 0; step < ML; ++step) {
        pdl_launch(gates_kernel, dim3(96), dim3(256), (size_t)163840, step);
        pdl_launch(fused_kernel, dim3(BB), dim3(1024), (size_t)0,
                   b_ih, b_hh, wo, bo, bs, step);
    }

    // all outputs at once (off the critical path)
    pdl_launch(out_final_kernel, dim3(ML * BB / 8), dim3(512), (size_t)0,
               bout, out);
}

// round 16
// speedup vs baseline: 1.6000x; 1.0424x over previous
#include <cuda_runtime.h>
#include <cuda_bf16.h>
#include <cuda_fp16.h>
#include <mma.h>
#include <math.h>

using namespace nvcuda;

#define BB 128
#define TT 256
#define LL 512
#define HH 512
#define CC 95
#define ML 26

// ---------------- device scratch (static: no runtime allocation) ----------------
__device__ __align__(16) __half g_x16[BB * TT * LL];            // 32 MB (fp16)
__device__ __align__(16) __half g_xEmb16[BB * TT * HH];         // 32 MB (fp16)
__device__ __align__(16) __half g_Wi16[LL * HH];                // fp16
__device__ __align__(16) __half g_Ws16[HH * HH];                // fp16
__device__ __align__(16) __nv_bfloat16 g_Wih16[1536 * 1024];
__device__ __align__(16) __nv_bfloat16 g_Whh16[1536 * 512];
__device__ __align__(16) __nv_bfloat16 g_embSeq[ML * BB * HH];
__device__ __align__(16) float g_giEmb[ML * BB * 1536];         // 20 MB
__device__ __align__(16) float g_WoutT[CC * HH];
__device__ __align__(16) float g_hHist[ML * BB * HH];           // 6.8 MB
__device__ __align__(16) __nv_bfloat16 g_h16[BB * HH];
__device__ __align__(16) __nv_bfloat16 g_ctx16[BB * HH];
__device__ __align__(16) float g_gates[BB * 3072];

// ---------------- PDL intrinsics -------------------------------------------------
__device__ __forceinline__ void gdc_wait() {
    asm volatile("griddepcontrol.wait;" ::: "memory");
}
__device__ __forceinline__ void gdc_launch() {
    asm volatile("griddepcontrol.launch_dependents;" ::: "memory");
}

// ---------------- fast math ------------------------------------------------------
__device__ __forceinline__ __half2 tanh2(__half2 x) {
    __half2 y;
    asm("tanh.approx.f16x2 %0, %1;"
        : "=r"(*(unsigned*)&y) : "r"(*(unsigned*)&x));
    return y;
}

__device__ __forceinline__ float fast_rcp_pos(float q) {
    float r = __uint_as_float(0x7EF127EAu - __float_as_uint(q));
    r = r * (2.0f - q * r);
    r = r * (2.0f - q * r);
    return r;
}

__device__ __forceinline__ float fast_tanh(float x) {  // accurate FMA-only (GRU n)
    float cx = fminf(fmaxf(x, -7.90531110763549805f), 7.90531110763549805f);
    float x2 = cx * cx;
    float p = fmaf(x2, -8.60467152213735e-11f, 5.12229709037114e-08f);
    p = fmaf(p, x2, 1.48572235717979e-05f);
    p = fmaf(p, x2, 6.37261928875436e-04f);
    p = fmaf(p, x2, 4.89352455891786e-03f);
    p = cx * p;
    float q = fmaf(x2, 1.19825839466702e-06f, 1.18534705686654e-04f);
    q = fmaf(q, x2, 2.26843463243900e-03f);
    q = fmaf(q, x2, 4.89352518554385e-03f);
    return p * fast_rcp_pos(q);
}

// ---------------- ONE merged prep kernel (all one-time conversions) --------------
__device__ __forceinline__ void cvt4(const float* __restrict__ src,
                                     __nv_bfloat16* __restrict__ dst, int i) {
    float4 v = *(const float4*)(src + i);
    __nv_bfloat162* o = (__nv_bfloat162*)(dst + i);
    o[0] = __floats2bfloat162_rn(v.x, v.y);
    o[1] = __floats2bfloat162_rn(v.z, v.w);
}

__device__ __forceinline__ void cvt4h(const float* __restrict__ src,
                                      __half* __restrict__ dst, int i) {
    float4 v = *(const float4*)(src + i);
    __half2* o = (__half2*)(dst + i);
    o[0] = __floats2half2_rn(v.x, v.y);
    o[1] = __floats2half2_rn(v.z, v.w);
}

__global__ void prep_kernel(const float* __restrict__ x,
                            const float* __restrict__ Wi,
                            const float* __restrict__ Ws,
                            const float* __restrict__ W_ih,
                            const float* __restrict__ W_hh,
                            const float* __restrict__ Wout,
                            const float* __restrict__ emb,
                            const int* __restrict__ targets) {
    const int blk = blockIdx.x;
    const int tid = threadIdx.x;
    if (blk < 16384) {                       // x -> fp16
        cvt4h(x, g_x16, blk * 1024 + tid * 4);
    } else if (blk < 16640) {                // Wi -> fp16
        cvt4h(Wi, g_Wi16, (blk - 16384) * 1024 + tid * 4);
    } else if (blk < 16896) {                // Ws -> fp16
        cvt4h(Ws, g_Ws16, (blk - 16640) * 1024 + tid * 4);
    } else if (blk < 18432) {                // W_ih
        cvt4(W_ih, g_Wih16, (blk - 16896) * 1024 + tid * 4);
    } else if (blk < 19200) {                // W_hh
        cvt4(W_hh, g_Whh16, (blk - 18432) * 1024 + tid * 4);
    } else if (blk < 19295) {                // Wout transpose
        int c = blk - 19200;
        g_WoutT[c * HH + tid] = Wout[tid * CC + c];
        g_WoutT[c * HH + tid + 256] = Wout[(tid + 256) * CC + c];
    } else if (blk < 20959) {                // teacher-forced emb gather (bf16)
        int e = (blk - 19295) * 1024 + tid * 4;
        int m = e >> 9, k = e & 511;
        int step = m >> 7, b = m & 127;
        int y = (step == 0) ? CC : targets[b * ML + step - 1];
        float4 v = *(const float4*)(emb + y * HH + k);
        __nv_bfloat162* o = (__nv_bfloat162*)(g_embSeq + (size_t)m * HH + k);
        o[0] = __floats2bfloat162_rn(v.x, v.y);
        o[1] = __floats2bfloat162_rn(v.z, v.w);
    } else {                                 // h16 = 0
        int i = (blk - 20959) * 1024 + tid * 4;
        __nv_bfloat162 z = __floats2bfloat162_rn(0.f, 0.f);
        __nv_bfloat162* o = (__nv_bfloat162*)(g_h16 + i);
        o[0] = z;
        o[1] = z;
    }
}

// ---------------- one-time: xEmb = x @ Wi + bi (fp16 wmma -> fp16 out) -----------
__global__ void xemb_wmma_kernel(const float* __restrict__ bias) {
    extern __shared__ char dyn[];
    __half (*As)[32] = (__half(*)[32])dyn;
    __half (*Bs)[128] = (__half(*)[128])(dyn + 8192);
    float (*Co)[128] = (float(*)[128])(dyn + 16384);
    const int tid = threadIdx.x;
    const int wid = tid >> 5;
    const int m0 = blockIdx.y * 128;
    const int n0 = blockIdx.x * 128;
    const int warpM = wid & 3;
    const int warpN = wid >> 2;

    wmma::fragment<wmma::accumulator, 16, 16, 16, float> c[2][4];
#pragma unroll
    for (int i = 0; i < 2; ++i)
#pragma unroll
        for (int j = 0; j < 4; ++j) wmma::fill_fragment(c[i][j], 0.f);

    for (int k0 = 0; k0 < 512; k0 += 32) {
#pragma unroll
        for (int i = 0; i < 2; ++i) {
            int idx = tid + i * 256;
            int m = idx >> 2, kq = idx & 3;
            *(uint4*)&As[m][kq * 8] =
                *(const uint4*)&g_x16[(size_t)(m0 + m) * 512 + k0 + kq * 8];
        }
#pragma unroll
        for (int i = 0; i < 2; ++i) {
            int idx = tid + i * 256;
            int k = idx >> 4, q = idx & 15;
            *(uint4*)&Bs[k][q * 8] =
                *(const uint4*)&g_Wi16[(size_t)(k0 + k) * 512 + n0 + q * 8];
        }
        __syncthreads();
#pragma unroll
        for (int kk = 0; kk < 32; kk += 16) {
            wmma::fragment<wmma::matrix_a, 16, 16, 16, __half, wmma::row_major> a[2];
            wmma::fragment<wmma::matrix_b, 16, 16, 16, __half, wmma::row_major> b[4];
#pragma unroll
            for (int i = 0; i < 2; ++i)
                wmma::load_matrix_sync(a[i], &As[warpM * 32 + i * 16][kk], 32);
#pragma unroll
            for (int j = 0; j < 4; ++j)
                wmma::load_matrix_sync(b[j], &Bs[kk][warpN * 64 + j * 16], 128);
#pragma unroll
            for (int i = 0; i < 2; ++i)
#pragma unroll
                for (int j = 0; j < 4; ++j)
                    wmma::mma_sync(c[i][j], a[i], b[j], c[i][j]);
        }
        __syncthreads();
    }
#pragma unroll
    for (int i = 0; i < 2; ++i)
#pragma unroll
        for (int j = 0; j < 4; ++j)
            wmma::store_matrix_sync(&Co[warpM * 32 + i * 16][warpN * 64 + j * 16],
                                    c[i][j], 128, wmma::mem_row_major);
    __syncthreads();
#pragma unroll
    for (int it = 0; it < 64; ++it) {
        int idx = it * 256 + tid;
        int m = idx >> 7, cc = idx & 127;
        g_xEmb16[(size_t)(m0 + m) * 512 + n0 + cc] =
            __float2half(Co[m][cc] + bias[n0 + cc]);
    }
}

// ------ one-time: giEmb = embSeq @ W_ih[:, :512]^T  [3328,1536] fp32 -------------
__global__ void giemb_wmma_kernel() {
    __shared__ __nv_bfloat16 As[128][32];
    __shared__ __nv_bfloat16 Bs[64][32];
    const int tid = threadIdx.x;
    const int wid = tid >> 5;
    const int m0 = blockIdx.y * 128;
    const int n0 = blockIdx.x * 64;

    wmma::fragment<wmma::accumulator, 16, 16, 16, float> c[4];
#pragma unroll
    for (int j = 0; j < 4; ++j) wmma::fill_fragment(c[j], 0.f);

    for (int k0 = 0; k0 < 512; k0 += 32) {
#pragma unroll
        for (int i = 0; i < 2; ++i) {
            int idx = tid + i * 256;
            int m = idx >> 2, kq = idx & 3;
            *(uint4*)&As[m][kq * 8] =
                *(const uint4*)&g_embSeq[(size_t)(m0 + m) * 512 + k0 + kq * 8];
        }
        {
            int j = tid >> 2, kq = tid & 3;
            *(uint4*)&Bs[j][kq * 8] =
                *(const uint4*)&g_Wih16[(size_t)(n0 + j) * 1024 + k0 + kq * 8];
        }
        __syncthreads();
#pragma unroll
        for (int kk = 0; kk < 32; kk += 16) {
            wmma::fragment<wmma::matrix_a, 16, 16, 16, __nv_bfloat16, wmma::row_major> a;
            wmma::load_matrix_sync(a, &As[wid * 16][kk], 32);
#pragma unroll
            for (int j = 0; j < 4; ++j) {
                wmma::fragment<wmma::matrix_b, 16, 16, 16, __nv_bfloat16, wmma::col_major> bf;
                wmma::load_matrix_sync(bf, &Bs[j * 16][kk], 32);
                wmma::mma_sync(c[j], a, bf, c[j]);
            }
        }
        __syncthreads();
    }
#pragma unroll
    for (int j = 0; j < 4; ++j)
        wmma::store_matrix_sync(&g_giEmb[(size_t)(m0 + wid * 16) * 1536 + n0 + j * 16],
                                c[j], 1536, wmma::mem_row_major);
}

// ---------------- attention body: half2-FMA e-score + half2 ctx ------------------
__device__ __forceinline__ void attn_body(int b, int tid,
                                          const float* sE, const float* wos,
                                          float* ew, float* red, float* redv,
                                          float* sPart, const float* bo) {
    const int lane = tid & 31, warp = tid >> 5;
    const __half2 hz = __floats2half2_rn(0.f, 0.f);

    // ---- e-scores: warp handles 8 t; lane owns cols [lane*8,+8) and [256+lane*8,+8)
    {
        __half2 wo2[8], sE2[8];
        {
            float4 w0 = *(const float4*)&wos[lane * 8];
            float4 w1 = *(const float4*)&wos[lane * 8 + 4];
            float4 w2 = *(const float4*)&wos[256 + lane * 8];
            float4 w3 = *(const float4*)&wos[256 + lane * 8 + 4];
            wo2[0] = __floats2half2_rn(w0.x, w0.y);
            wo2[1] = __floats2half2_rn(w0.z, w0.w);
            wo2[2] = __floats2half2_rn(w1.x, w1.y);
            wo2[3] = __floats2half2_rn(w1.z, w1.w);
            wo2[4] = __floats2half2_rn(w2.x, w2.y);
            wo2[5] = __floats2half2_rn(w2.z, w2.w);
            wo2[6] = __floats2half2_rn(w3.x, w3.y);
            wo2[7] = __floats2half2_rn(w3.z, w3.w);
            float4 s0 = *(const float4*)&sE[lane * 8];
            float4 s1 = *(const float4*)&sE[lane * 8 + 4];
            float4 s2 = *(const float4*)&sE[256 + lane * 8];
            float4 s3 = *(const float4*)&sE[256 + lane * 8 + 4];
            sE2[0] = __floats2half2_rn(s0.x, s0.y);
            sE2[1] = __floats2half2_rn(s0.z, s0.w);
            sE2[2] = __floats2half2_rn(s1.x, s1.y);
            sE2[3] = __floats2half2_rn(s1.z, s1.w);
            sE2[4] = __floats2half2_rn(s2.x, s2.y);
            sE2[5] = __floats2half2_rn(s2.z, s2.w);
            sE2[6] = __floats2half2_rn(s3.x, s3.y);
            sE2[7] = __floats2half2_rn(s3.z, s3.w);
        }
        const float bov = bo[0];
#pragma unroll
        for (int r = 0; r < 8; ++r) {
            int t = warp * 8 + r;
            const uint4* row = (const uint4*)(g_xEmb16 + ((size_t)(b * 256 + t)) * 512);
            uint4 u0 = row[lane];        // cols [lane*8, +8)
            uint4 u1 = row[lane + 32];   // cols [256+lane*8, +8)
            const __half2* x0 = (const __half2*)&u0;
            const __half2* x1 = (const __half2*)&u1;
            __half2 a0h = hz, a1h = hz;
#pragma unroll
            for (int j = 0; j < 4; ++j) {
                a0h = __hfma2(wo2[j], tanh2(__hadd2(x0[j], sE2[j])), a0h);
                a1h = __hfma2(wo2[4 + j], tanh2(__hadd2(x1[j], sE2[4 + j])), a1h);
            }
            float2 ff = __half22float2(__hadd2(a0h, a1h));
            float acc = ff.x + ff.y;
#pragma unroll
            for (int off = 16; off > 0; off >>= 1)
                acc += __shfl_xor_sync(0xffffffffu, acc, off);
            if (lane == 0) ew[t] = acc + bov;
        }
    }
    __syncthreads();

    // ---- softmax over ew[256] ----
    if (tid < 256) {
        float v = ew[tid];
        float m = v;
#pragma unroll
        for (int off = 16; off > 0; off >>= 1)
            m = fmaxf(m, __shfl_xor_sync(0xffffffffu, m, off));
        if ((tid & 31) == 0) red[tid >> 5] = m;
    }
    __syncthreads();
    if (tid == 0) {
        float m = red[0];
#pragma unroll
        for (int w = 1; w < 8; ++w) m = fmaxf(m, red[w]);
        redv[0] = m;
    }
    __syncthreads();
    if (tid < 256) {
        float p = __expf(ew[tid] - redv[0]);
        ew[tid] = p;
        float s = p;
#pragma unroll
        for (int off = 16; off > 0; off >>= 1)
            s += __shfl_xor_sync(0xffffffffu, s, off);
        if ((tid & 31) == 0) red[8 + (tid >> 5)] = s;
    }
    __syncthreads();
    if (tid == 0) {
        float s = 0.f;
#pragma unroll
        for (int w = 0; w < 8; ++w) s += red[8 + w];
        redv[1] = 1.0f / s;
    }
    __syncthreads();
    if (tid < 256) ew[tid] *= redv[1];
    __syncthreads();

    // ---- ctx = aw @ x[b]: 16-way t-split, half2 FMA chains (flush every 4 t) ----
    {
        const int tq = tid >> 6;           // 0..15, t in [tq*16, +16)
        const int g = tid & 63;            // cols [g*8, +8)
        float f0 = 0.f, f1 = 0.f, f2 = 0.f, f3 = 0.f;
        float f4 = 0.f, f5 = 0.f, f6 = 0.f, f7 = 0.f;
        __half2 c0 = hz, c1 = hz, c2 = hz, c3 = hz;
        const uint4* xb = (const uint4*)(g_x16 + ((size_t)b * 256 + tq * 16) * 512) + g;
#pragma unroll
        for (int tt = 0; tt < 16; ++tt) {
            __half2 aw2 = __float2half2_rn(ew[tq * 16 + tt]);
            uint4 u = xb[(size_t)tt * 64];
            const __half2* x2 = (const __half2*)&u;
            c0 = __hfma2(aw2, x2[0], c0);
            c1 = __hfma2(aw2, x2[1], c1);
            c2 = __hfma2(aw2, x2[2], c2);
            c3 = __hfma2(aw2, x2[3], c3);
            if ((tt & 3) == 3) {
                float2 t0 = __half22float2(c0);
                float2 t1 = __half22float2(c1);
                float2 t2 = __half22float2(c2);
                float2 t3 = __half22float2(c3);
                f0 += t0.x; f1 += t0.y; f2 += t1.x; f3 += t1.y;
                f4 += t2.x; f5 += t2.y; f6 += t3.x; f7 += t3.y;
                c0 = hz; c1 = hz; c2 = hz; c3 = hz;
            }
        }
        float* p = &sPart[tq * 512 + g * 8];
        *(float4*)p = make_float4(f0, f1, f2, f3);
        *(float4*)(p + 4) = make_float4(f4, f5, f6, f7);
    }
    __syncthreads();
    if (tid < 512) {
        float c = 0.f;
#pragma unroll
        for (int i = 0; i < 16; ++i) c += sPart[i * 512 + tid];
        g_ctx16[b * 512 + tid] = __float2bfloat16(c);
    }
}

// ---------------- step 0 attention (h = 0 -> sEmb = bs) --------------------------
__global__ __launch_bounds__(1024, 1)
void attn0_kernel(const float* __restrict__ wo,
                  const float* __restrict__ bo,
                  const float* __restrict__ bs) {
    const int b = blockIdx.x;
    const int tid = threadIdx.x;
    __shared__ __align__(16) float sE[512];
    __shared__ __align__(16) float wos[512];
    __shared__ __align__(16) float ew[256];
    __shared__ float red[16], redv[2];
    __shared__ __align__(16) float sPart[16 * 512];
    if (tid < 512) {
        sE[tid] = bs[tid];
        wos[tid] = wo[tid];
    }
    __syncthreads();
    attn_body(b, tid, sE, wos, ew, red, redv, sPart, bo);
}

// ---------- per-step gates GEMM: PDL + full-tile smem staging --------------------
// grid 96 (48 gi + 48 gh), 256 threads. dyn smem: A 128x512 (128KB) + B 32x512 (32KB)
__global__ void gates_kernel(int step) {
    extern __shared__ char dyn[];
    __nv_bfloat16 (*As)[512] = (__nv_bfloat16(*)[512])dyn;
    __nv_bfloat16 (*Ball)[512] = (__nv_bfloat16(*)[512])(dyn + 131072);
    const int tid = threadIdx.x;
    const int wid = tid >> 5;
    const bool hh = blockIdx.x >= 48;
    const __nv_bfloat16* A = hh ? g_h16 : g_ctx16;
    const __nv_bfloat16* W = hh ? g_Whh16 : g_Wih16;
    const int ldw = hh ? 512 : 1024;
    const int koff = hh ? 0 : 512;
    const int n0 = (hh ? blockIdx.x - 48 : blockIdx.x) * 32;
    const int outc = (hh ? 1536 : 0) + n0;

    // ---- PDL prologue: everything independent of the predecessor ----
#pragma unroll
    for (int i = 0; i < 8; ++i) {
        int idx = tid + i * 256;         // 2048 uint4, 64 per row
        int j = idx >> 6, q = idx & 63;
        *(uint4*)&Ball[j][q * 8] =
            *(const uint4*)&W[(size_t)(n0 + j) * ldw + koff + q * 8];
    }
    wmma::fragment<wmma::accumulator, 16, 16, 16, float> c[2];
    if (hh) {
        wmma::fill_fragment(c[0], 0.f);
        wmma::fill_fragment(c[1], 0.f);
    } else {
        const float* gi = g_giEmb + ((size_t)step * 128 + wid * 16) * 1536 + n0;
        wmma::load_matrix_sync(c[0], gi, 1536, wmma::mem_row_major);
        wmma::load_matrix_sync(c[1], gi + 16, 1536, wmma::mem_row_major);
    }

    gdc_wait();

    // stage full A (128x512 bf16 = 8192 uint4, 64 per row)
#pragma unroll
    for (int i = 0; i < 32; ++i) {
        int idx = tid + i * 256;
        int m = idx >> 6, q = idx & 63;
        *(uint4*)&As[m][q * 8] = *(const uint4*)&A[(size_t)m * 512 + q * 8];
    }
    __syncthreads();

#pragma unroll 8
    for (int kk = 0; kk < 512; kk += 16) {
        wmma::fragment<wmma::matrix_a, 16, 16, 16, __nv_bfloat16, wmma::row_major> a;
        wmma::load_matrix_sync(a, &As[wid * 16][kk], 512);
#pragma unroll
        for (int j = 0; j < 2; ++j) {
            wmma::fragment<wmma::matrix_b, 16, 16, 16, __nv_bfloat16, wmma::col_major> bf;
            wmma::load_matrix_sync(bf, &Ball[j * 16][kk], 512);
            wmma::mma_sync(c[j], a, bf, c[j]);
        }
    }
#pragma unroll
    for (int j = 0; j < 2; ++j)
        wmma::store_matrix_sync(&g_gates[(size_t)(wid * 16) * 3072 + outc + j * 16],
                                c[j], 3072, wmma::mem_row_major);
    gdc_launch();
}

// ------ fused: GRU pointwise + h store + sEmb + attention (PDL) ------------------
// grid 128, 1024 threads
__global__ __launch_bounds__(1024, 1)
void fused_kernel(const float* __restrict__ b_ih,
                  const float* __restrict__ b_hh,
                  const float* __restrict__ wo,
                  const float* __restrict__ bo,
                  const float* __restrict__ bs,
                  int step) {
    const int b = blockIdx.x;
    const int tid = threadIdx.x;
    __shared__ __align__(16) float hs[512];
    __shared__ __align__(16) float sE[512];
    __shared__ __align__(16) float wos[512];
    __shared__ __align__(16) float ew[256];
    __shared__ float red[16], redv[2];
    __shared__ __align__(16) float sPart[16 * 512];
    const __half2 hz = __floats2half2_rn(0.f, 0.f);

    // PDL prologue: independent loads
    float bi_r = 0.f, bi_z = 0.f, bi_n = 0.f, bh_r = 0.f, bh_z = 0.f, bh_n = 0.f;
    float h_prev = 0.f;
    if (tid < 512) {
        wos[tid] = wo[tid];
        bi_r = b_ih[tid];
        bi_z = b_ih[tid + 512];
        bi_n = b_ih[tid + 1024];
        bh_r = b_hh[tid];
        bh_z = b_hh[tid + 512];
        bh_n = b_hh[tid + 1024];
        if (step > 0)
            h_prev = g_hHist[((size_t)(step - 1) * BB + b) * 512 + tid];
    }

    gdc_wait();  // wait for gates(step)

    // ---- GRU pointwise update ----
    if (tid < 512) {
        const float* g = g_gates + b * 3072;
        float gir = g[tid] + bi_r;
        float giz = g[tid + 512] + bi_z;
        float gin = g[tid + 1024] + bi_n;
        float ghr = g[tid + 1536] + bh_r;
        float ghz = g[tid + 2048] + bh_z;
        float ghn = g[tid + 2560] + bh_n;
        float r = 1.f / (1.f + __expf(-(gir + ghr)));
        float z = 1.f / (1.f + __expf(-(giz + ghz)));
        float n = fast_tanh(gin + r * ghn);
        float hv = (1.f - z) * n + z * h_prev;
        g_hHist[((size_t)step * BB + b) * 512 + tid] = hv;
        g_h16[b * 512 + tid] = __float2bfloat16(hv);
        hs[tid] = hv;
    }
    __syncthreads();

    if (step == ML - 1) {
        gdc_launch();
        return;
    }

    // ---- sEmb = h @ Ws + bs (16-way k-split, half2 FMA chains) ----
    {
        const int ks = tid >> 6;          // 0..15, k in [ks*32, +32)
        const int g = tid & 63;           // cols [g*8, +8)
        float f0 = 0.f, f1 = 0.f, f2 = 0.f, f3 = 0.f;
        float f4 = 0.f, f5 = 0.f, f6 = 0.f, f7 = 0.f;
        __half2 c0 = hz, c1 = hz, c2 = hz, c3 = hz;
        const uint4* wrow = (const uint4*)(g_Ws16 + (size_t)(ks * 32) * 512) + g;
#pragma unroll
        for (int kk = 0; kk < 32; ++kk) {
            __half2 hk2 = __float2half2_rn(hs[ks * 32 + kk]);
            uint4 u = wrow[(size_t)kk * 64];
            const __half2* w2 = (const __half2*)&u;
            c0 = __hfma2(hk2, w2[0], c0);
            c1 = __hfma2(hk2, w2[1], c1);
            c2 = __hfma2(hk2, w2[2], c2);
            c3 = __hfma2(hk2, w2[3], c3);
            if ((kk & 7) == 7) {
                float2 t0 = __half22float2(c0);
                float2 t1 = __half22float2(c1);
                float2 t2 = __half22float2(c2);
                float2 t3 = __half22float2(c3);
                f0 += t0.x; f1 += t0.y; f2 += t1.x; f3 += t1.y;
                f4 += t2.x; f5 += t2.y; f6 += t3.x; f7 += t3.y;
                c0 = hz; c1 = hz; c2 = hz; c3 = hz;
            }
        }
        float* p = &sPart[ks * 512 + g * 8];
        *(float4*)p = make_float4(f0, f1, f2, f3);
        *(float4*)(p + 4) = make_float4(f4, f5, f6, f7);
    }
    __syncthreads();
    if (tid < 512) {
        float s = bs[tid];
#pragma unroll
        for (int i = 0; i < 16; ++i) s += sPart[i * 512 + tid];
        sE[tid] = s;
    }
    __syncthreads();

    attn_body(b, tid, sE, wos, ew, red, redv, sPart, bo);
    gdc_launch();
}

// ------ final: logits + log-softmax for all 3328 rows (PDL) ----------------------
__global__ void out_final_kernel(const float* __restrict__ bout,
                                 float* __restrict__ out) {
    const int m0 = blockIdx.x * 8;
    const int tid = threadIdx.x;
    __shared__ float hs8[8][512];
    __shared__ float lg[8][96];

    gdc_wait();

    for (int i = tid; i < 8 * 512; i += 512)
        hs8[i >> 9][i & 511] = g_hHist[(size_t)m0 * 512 + i];
    __syncthreads();

    for (int i = tid; i < 8 * CC; i += 512) {
        int r = i / CC, c = i % CC;
        const float4* wp = (const float4*)(g_WoutT + c * 512);
        const float4* hp = (const float4*)hs8[r];
        float acc = 0.f;
#pragma unroll 16
        for (int k = 0; k < 128; ++k) {
            float4 h4 = hp[k], w4 = wp[k];
            acc = fmaf(h4.x, w4.x, acc);
            acc = fmaf(h4.y, w4.y, acc);
            acc = fmaf(h4.z, w4.z, acc);
            acc = fmaf(h4.w, w4.w, acc);
        }
        lg[r][c] = acc + bout[c];
    }
    __syncthreads();

    const int warp = tid >> 5, lane = tid & 31;
    if (warp < 8) {
        float v0 = (lane < CC) ? lg[warp][lane] : -1e30f;
        float v1 = (lane + 32 < CC) ? lg[warp][lane + 32] : -1e30f;
        float v2 = (lane + 64 < CC) ? lg[warp][lane + 64] : -1e30f;
        float m = fmaxf(v0, fmaxf(v1, v2));
#pragma unroll
        for (int off = 16; off > 0; off >>= 1)
            m = fmaxf(m, __shfl_xor_sync(0xffffffffu, m, off));
        float s = ((lane < CC) ? __expf(v0 - m) : 0.f) +
                  ((lane + 32 < CC) ? __expf(v1 - m) : 0.f) +
                  ((lane + 64 < CC) ? __expf(v2 - m) : 0.f);
#pragma unroll
        for (int off = 16; off > 0; off >>= 1)
            s += __shfl_xor_sync(0xffffffffu, s, off);
        float lse = m + logf(s);
        float* o = out + (size_t)(m0 + warp) * CC;
        if (lane < CC) o[lane] = v0 - lse;
        if (lane + 32 < CC) o[lane + 32] = v1 - lse;
        if (lane + 64 < CC) o[lane + 64] = v2 - lse;
    }
}

// ---------------- PDL launch helper ----------------------------------------------
template <class F, class... A>
static inline void pdl_launch(F f, dim3 g, dim3 b, size_t smem, A... args) {
    cudaLaunchConfig_t cfg = {};
    cfg.gridDim = g;
    cfg.blockDim = b;
    cfg.dynamicSmemBytes = smem;
    cfg.stream = 0;
    cudaLaunchAttribute at[1];
    at[0].id = cudaLaunchAttributeProgrammaticStreamSerialization;
    at[0].val.programmaticStreamSerializationAllowed = 1;
    cfg.attrs = at;
    cfg.numAttrs = 1;
    cudaLaunchKernelEx(&cfg, f, args...);
}

// --------------------------------- launcher --------------------------------------
extern "C" void kernel_launch(void* const* d_in, const int* in_sizes, int n_in,
                              void* d_out, int out_size) {
    (void)in_sizes; (void)n_in; (void)out_size;
    const float* x       = (const float*)d_in[0];
    const int*   targets = (const int*)  d_in[1];
    const float* emb     = (const float*)d_in[2];
    const float* Wi      = (const float*)d_in[3];
    const float* bi      = (const float*)d_in[4];
    const float* Ws      = (const float*)d_in[5];
    const float* bs      = (const float*)d_in[6];
    const float* wo      = (const float*)d_in[7];
    const float* bo      = (const float*)d_in[8];
    const float* W_ih    = (const float*)d_in[9];
    const float* W_hh    = (const float*)d_in[10];
    const float* b_ih    = (const float*)d_in[11];
    const float* b_hh    = (const float*)d_in[12];
    const float* Wout    = (const float*)d_in[13];
    const float* bout    = (const float*)d_in[14];
    float* out = (float*)d_out;

    static bool attr_set = false;
    if (!attr_set) {
        cudaFuncSetAttribute(xemb_wmma_kernel,
                             cudaFuncAttributeMaxDynamicSharedMemorySize, 81920);
        cudaFuncSetAttribute(gates_kernel,
                             cudaFuncAttributeMaxDynamicSharedMemorySize, 163840);
        attr_set = true;
    }

    // one-time (merged): launch #0
    prep_kernel<<<21023, 256>>>(x, Wi, Ws, W_ih, W_hh, Wout, emb, targets);
    // launch #1
    xemb_wmma_kernel<<<dim3(4, 256), 256, 81920>>>(bi);
    // launch #2
    giemb_wmma_kernel<<<dim3(1536 / 64, ML * BB / 128), 256>>>();
    // launch #3: step 0 attention (h = 0)
    attn0_kernel<<<BB, 1024>>>(wo, bo, bs);

    for (int step = 0; step < ML; ++step) {
        pdl_launch(gates_kernel, dim3(96), dim3(256), (size_t)163840, step);
        pdl_launch(fused_kernel, dim3(BB), dim3(1024), (size_t)0,
                   b_ih, b_hh, wo, bo, bs, step);
    }

    // all outputs at once (off the critical path)
    pdl_launch(out_final_kernel, dim3(ML * BB / 8), dim3(512), (size_t)0,
               bout, out);
}